// round 5
// baseline (speedup 1.0000x reference)
#include <cuda_runtime.h>
#include <math.h>

// Problem constants
#define B_   4096
#define T_   26
#define IN_  512
#define H_   512
#define NC_  97
#define NE_  256
#define K1_  (IN_ + NE_)   // 768
#define G_   (4 * H_)      // 2048 (gate dim)
#define M1_  (B_ * T_)     // 106496

// ---------------------------------------------------------------------------
// Scratch (device globals: no allocation allowed anywhere)
// ---------------------------------------------------------------------------
__device__ float g_gx[(size_t)M1_ * G_];     // [B*T, 4H] precomputed input gates (872 MB)
__device__ float g_gates[(size_t)B_ * G_];   // [B, 4H] per-step gate pre-activations
__device__ float g_h0[B_ * H_];              // h ping-pong
__device__ float g_h1[B_ * H_];
__device__ float g_c[B_ * H_];               // cell state (updated in place)

// ---------------------------------------------------------------------------
// Zero-init h0 and c (kernel_launch must be deterministic across calls)
// ---------------------------------------------------------------------------
__global__ void zero_state_kernel() {
    int i = blockIdx.x * blockDim.x + threadIdx.x;
    if (i < B_ * H_) {
        g_h0[i] = 0.0f;
        g_c[i]  = 0.0f;
    }
}

// ---------------------------------------------------------------------------
// Kernel 1: gx[m][n] = sum_k x[m][k] * W_ih[n][k] + b_ih[n]
//   x[m] = concat(batch_H[m], emb_table[text[m]]),  m = b*T + t
//   M = 106496, N = 2048, K = 768.  128x128x16 tile, 8x8 micro-tile, 256 thr.
// ---------------------------------------------------------------------------
__global__ void __launch_bounds__(256, 2) gx_kernel(
    const float* __restrict__ bh,    // [M1, 512]
    const int*   __restrict__ text,  // [M1]
    const float* __restrict__ emb,   // [98, 256]
    const float* __restrict__ Wih,   // [2048, 768]
    const float* __restrict__ bih)   // [2048]
{
    __shared__ float As[16][132];   // [k][m], pad 132 (16B-aligned rows, reduced ST conflicts)
    __shared__ float Bs[16][132];   // [k][n]

    const int tid = threadIdx.x;
    const int tx  = tid & 15;       // n micro-col
    const int ty  = tid >> 4;       // m micro-row
    const int m0  = blockIdx.x * 128;
    const int n0  = blockIdx.y * 128;

    float acc[8][8];
#pragma unroll
    for (int i = 0; i < 8; i++)
#pragma unroll
        for (int j = 0; j < 8; j++) acc[i][j] = 0.0f;

    for (int k0 = 0; k0 < K1_; k0 += 16) {
#pragma unroll
        for (int l = 0; l < 2; l++) {
            int idx = l * 256 + tid;      // 0..511 -> (row, quad)
            int r = idx >> 2;
            int q = idx & 3;
            float4 v;
            if (k0 < IN_) {
                v = *(const float4*)(bh + (size_t)(m0 + r) * IN_ + k0 + q * 4);
            } else {
                int c = text[m0 + r];     // 0..97
                v = *(const float4*)(emb + (size_t)c * NE_ + (k0 - IN_) + q * 4);
            }
            As[q * 4 + 0][r] = v.x; As[q * 4 + 1][r] = v.y;
            As[q * 4 + 2][r] = v.z; As[q * 4 + 3][r] = v.w;

            float4 w = *(const float4*)(Wih + (size_t)(n0 + r) * K1_ + k0 + q * 4);
            Bs[q * 4 + 0][r] = w.x; Bs[q * 4 + 1][r] = w.y;
            Bs[q * 4 + 2][r] = w.z; Bs[q * 4 + 3][r] = w.w;
        }
        __syncthreads();

#pragma unroll
        for (int kk = 0; kk < 16; kk++) {
            float a[8], b[8];
#pragma unroll
            for (int i = 0; i < 8; i++) a[i] = As[kk][ty * 8 + i];
#pragma unroll
            for (int j = 0; j < 8; j++) b[j] = Bs[kk][tx * 8 + j];
#pragma unroll
            for (int i = 0; i < 8; i++)
#pragma unroll
                for (int j = 0; j < 8; j++)
                    acc[i][j] = fmaf(a[i], b[j], acc[i][j]);
        }
        __syncthreads();
    }

#pragma unroll
    for (int i = 0; i < 8; i++) {
        size_t m = (size_t)(m0 + ty * 8 + i);
#pragma unroll
        for (int j = 0; j < 8; j++) {
            int n = n0 + tx * 8 + j;
            g_gx[m * G_ + n] = acc[i][j] + bih[n];
        }
    }
}

// ---------------------------------------------------------------------------
// Kernel 2a (per step t): gates[b][n] = h_in[b] . W_hh[n] + b_hh[n] + gx[b*T+t][n]
//   M = 4096 (batch), N = 2048, K = 512
// ---------------------------------------------------------------------------
__global__ void __launch_bounds__(256, 2) gates_kernel(
    const float* __restrict__ Whh,   // [2048, 512]
    const float* __restrict__ bhh,   // [2048]
    int t)
{
    const float* __restrict__ h_in = (t & 1) ? g_h1 : g_h0;

    __shared__ float As[16][132];
    __shared__ float Bs[16][132];

    const int tid = threadIdx.x;
    const int tx  = tid & 15;
    const int ty  = tid >> 4;
    const int m0  = blockIdx.x * 128;   // batch
    const int n0  = blockIdx.y * 128;   // gate col

    float acc[8][8];
#pragma unroll
    for (int i = 0; i < 8; i++)
#pragma unroll
        for (int j = 0; j < 8; j++) acc[i][j] = 0.0f;

    for (int k0 = 0; k0 < H_; k0 += 16) {
#pragma unroll
        for (int l = 0; l < 2; l++) {
            int idx = l * 256 + tid;
            int r = idx >> 2;
            int q = idx & 3;
            float4 v = *(const float4*)(h_in + (size_t)(m0 + r) * H_ + k0 + q * 4);
            As[q * 4 + 0][r] = v.x; As[q * 4 + 1][r] = v.y;
            As[q * 4 + 2][r] = v.z; As[q * 4 + 3][r] = v.w;

            float4 w = *(const float4*)(Whh + (size_t)(n0 + r) * H_ + k0 + q * 4);
            Bs[q * 4 + 0][r] = w.x; Bs[q * 4 + 1][r] = w.y;
            Bs[q * 4 + 2][r] = w.z; Bs[q * 4 + 3][r] = w.w;
        }
        __syncthreads();

#pragma unroll
        for (int kk = 0; kk < 16; kk++) {
            float a[8], b[8];
#pragma unroll
            for (int i = 0; i < 8; i++) a[i] = As[kk][ty * 8 + i];
#pragma unroll
            for (int j = 0; j < 8; j++) b[j] = Bs[kk][tx * 8 + j];
#pragma unroll
            for (int i = 0; i < 8; i++)
#pragma unroll
                for (int j = 0; j < 8; j++)
                    acc[i][j] = fmaf(a[i], b[j], acc[i][j]);
        }
        __syncthreads();
    }

#pragma unroll
    for (int i = 0; i < 8; i++) {
        int m = m0 + ty * 8 + i;   // batch index
#pragma unroll
        for (int j = 0; j < 8; j++) {
            int n = n0 + tx * 8 + j;
            g_gates[(size_t)m * G_ + n] =
                acc[i][j] + bhh[n] + g_gx[((size_t)m * T_ + t) * G_ + n];
        }
    }
}

// ---------------------------------------------------------------------------
// Kernel 2b (per step t): LSTM pointwise update + write hiddens output
//   PyTorch gate order: i, f, g, o  (N-slices [0,512), [512,1024), ...)
// ---------------------------------------------------------------------------
__global__ void lstm_pointwise_kernel(float* __restrict__ out_hid, int t)
{
    float* __restrict__ h_out = (t & 1) ? g_h0 : g_h1;

    int idx = blockIdx.x * blockDim.x + threadIdx.x;   // 0 .. B*H-1
    if (idx >= B_ * H_) return;
    int b = idx >> 9;      // / 512
    int j = idx & 511;

    const float* gr = g_gates + (size_t)b * G_;
    float gi = gr[j];
    float gf = gr[j + H_];
    float gg = gr[j + 2 * H_];
    float go = gr[j + 3 * H_];

    float i_ = 1.0f / (1.0f + expf(-gi));
    float f_ = 1.0f / (1.0f + expf(-gf));
    float g_ = tanhf(gg);
    float o_ = 1.0f / (1.0f + expf(-go));

    float c = f_ * g_c[idx] + i_ * g_;
    float h = o_ * tanhf(c);

    g_c[idx]   = c;
    h_out[idx] = h;
    out_hid[((size_t)b * T_ + t) * H_ + j] = h;
}

// ---------------------------------------------------------------------------
// Kernel 3: probs[m][c] = hid[m] . W_gen[c] + b_gen[c]
//   M = 106496, N = 97 (tiled as 128 with guard), K = 512
// ---------------------------------------------------------------------------
__global__ void __launch_bounds__(256, 2) probs_kernel(
    const float* __restrict__ hid,   // [M1, 512]  (lives inside d_out)
    const float* __restrict__ Wg,    // [97, 512]
    const float* __restrict__ bg,    // [97]
    float* __restrict__ probs)       // [M1, 97]
{
    __shared__ float As[16][132];
    __shared__ float Bs[16][132];

    const int tid = threadIdx.x;
    const int tx  = tid & 15;
    const int ty  = tid >> 4;
    const int m0  = blockIdx.x * 128;

    float acc[8][8];
#pragma unroll
    for (int i = 0; i < 8; i++)
#pragma unroll
        for (int j = 0; j < 8; j++) acc[i][j] = 0.0f;

    for (int k0 = 0; k0 < H_; k0 += 16) {
#pragma unroll
        for (int l = 0; l < 2; l++) {
            int idx = l * 256 + tid;
            int r = idx >> 2;
            int q = idx & 3;
            float4 v = *(const float4*)(hid + (size_t)(m0 + r) * H_ + k0 + q * 4);
            As[q * 4 + 0][r] = v.x; As[q * 4 + 1][r] = v.y;
            As[q * 4 + 2][r] = v.z; As[q * 4 + 3][r] = v.w;

            float4 w = make_float4(0.f, 0.f, 0.f, 0.f);
            if (r < NC_)
                w = *(const float4*)(Wg + (size_t)r * H_ + k0 + q * 4);
            Bs[q * 4 + 0][r] = w.x; Bs[q * 4 + 1][r] = w.y;
            Bs[q * 4 + 2][r] = w.z; Bs[q * 4 + 3][r] = w.w;
        }
        __syncthreads();

#pragma unroll
        for (int kk = 0; kk < 16; kk++) {
            float a[8], b[8];
#pragma unroll
            for (int i = 0; i < 8; i++) a[i] = As[kk][ty * 8 + i];
#pragma unroll
            for (int j = 0; j < 8; j++) b[j] = Bs[kk][tx * 8 + j];
#pragma unroll
            for (int i = 0; i < 8; i++)
#pragma unroll
                for (int j = 0; j < 8; j++)
                    acc[i][j] = fmaf(a[i], b[j], acc[i][j]);
        }
        __syncthreads();
    }

#pragma unroll
    for (int i = 0; i < 8; i++) {
        size_t m = (size_t)(m0 + ty * 8 + i);
#pragma unroll
        for (int j = 0; j < 8; j++) {
            int n = tx * 8 + j;
            if (n < NC_)
                probs[m * NC_ + n] = acc[i][j] + bg[n];
        }
    }
}

// ---------------------------------------------------------------------------
// Launch: zero -> gx GEMM -> 26 x (gates GEMM + pointwise) -> probs GEMM
// Output layout: d_out = [probs (B*T*97) | output_hiddens (B*T*512)]
// ---------------------------------------------------------------------------
extern "C" void kernel_launch(void* const* d_in, const int* in_sizes, int n_in,
                              void* d_out, int out_size)
{
    const float* bh   = (const float*)d_in[0];
    const int*   text = (const int*)  d_in[1];
    const float* emb  = (const float*)d_in[2];
    const float* Wih  = (const float*)d_in[3];
    const float* Whh  = (const float*)d_in[4];
    const float* bih  = (const float*)d_in[5];
    const float* bhh  = (const float*)d_in[6];
    const float* Wg   = (const float*)d_in[7];
    const float* bg   = (const float*)d_in[8];

    float* out   = (float*)d_out;
    float* probs = out;                               // [M1, 97]
    float* hid   = out + (size_t)M1_ * NC_;           // [M1, 512]

    (void)in_sizes; (void)n_in; (void)out_size;

    zero_state_kernel<<<(B_ * H_ + 255) / 256, 256>>>();

    gx_kernel<<<dim3(M1_ / 128, G_ / 128), 256>>>(bh, text, emb, Wih, bih);

    for (int t = 0; t < T_; t++) {
        gates_kernel<<<dim3(B_ / 128, G_ / 128), 256>>>(Whh, bhh, t);
        lstm_pointwise_kernel<<<(B_ * H_) / 256, 256>>>(hid, t);
    }

    probs_kernel<<<dim3(M1_ / 128, 1), 256>>>(hid, Wg, bg, probs);
}

// round 7
// speedup vs baseline: 1.9436x; 1.9436x over previous
#include <cuda_runtime.h>
#include <cuda_bf16.h>
#include <stdint.h>
#include <math.h>

// Problem constants
#define B_   4096
#define T_   26
#define IN_  512
#define H_   512
#define NC_  97
#define NE_  256
#define K1_  (IN_ + NE_)   // 768
#define G_   (4 * H_)      // 2048
#define M1_  (B_ * T_)     // 106496

// Dynamic smem: 4 operand tiles (A_hi, A_lo, B_hi, B_lo), each 128 rows x 128B
#define SMEM_DYN (4 * 16384 + 256)

// ---------------------------------------------------------------------------
// Scratch (device globals: no allocation allowed anywhere)
// ---------------------------------------------------------------------------
__device__ float g_gx[(size_t)M1_ * G_];       // [B*T, 4H] input-gate preacts
__device__ float g_gates[(size_t)B_ * G_];     // [B, 4H] per-step gates
__device__ float g_c[B_ * H_];                 // cell state
__device__ __nv_bfloat16 g_xh[(size_t)M1_ * K1_];  // x split hi/lo
__device__ __nv_bfloat16 g_xl[(size_t)M1_ * K1_];
__device__ __nv_bfloat16 g_Hh[(size_t)M1_ * H_];   // hiddens hi/lo [b*T+t, H]
__device__ __nv_bfloat16 g_Hl[(size_t)M1_ * H_];
__device__ __nv_bfloat16 g_Wih_h[G_ * K1_];
__device__ __nv_bfloat16 g_Wih_l[G_ * K1_];
__device__ __nv_bfloat16 g_Whh_h[G_ * H_];
__device__ __nv_bfloat16 g_Whh_l[G_ * H_];
__device__ __nv_bfloat16 g_Wg_h[128 * H_];     // W_gen padded to 128 rows
__device__ __nv_bfloat16 g_Wg_l[128 * H_];

// ---------------------------------------------------------------------------
// PTX helpers (compute_103-safe: ldmatrix + mma.sync only, NO tcgen05)
// ---------------------------------------------------------------------------
__device__ __forceinline__ uint32_t smem_u32(const void* p) {
    uint32_t a;
    asm("{ .reg .u64 t; cvta.to.shared.u64 t, %1; cvt.u32.u64 %0, t; }"
        : "=r"(a) : "l"(p));
    return a;
}

__device__ __forceinline__ void ldmx4(uint32_t* r, uint32_t addr) {
    asm volatile("ldmatrix.sync.aligned.m8n8.x4.shared.b16 {%0,%1,%2,%3}, [%4];"
                 : "=r"(r[0]), "=r"(r[1]), "=r"(r[2]), "=r"(r[3]) : "r"(addr));
}

__device__ __forceinline__ void mma_bf16(float* d, const uint32_t* a,
                                         uint32_t b0, uint32_t b1) {
    asm volatile(
        "mma.sync.aligned.m16n8k16.row.col.f32.bf16.bf16.f32 "
        "{%0,%1,%2,%3}, {%4,%5,%6,%7}, {%8,%9}, {%0,%1,%2,%3};"
        : "+f"(d[0]), "+f"(d[1]), "+f"(d[2]), "+f"(d[3])
        : "r"(a[0]), "r"(a[1]), "r"(a[2]), "r"(a[3]), "r"(b0), "r"(b1));
}

// ---------------------------------------------------------------------------
// Small prep kernels
// ---------------------------------------------------------------------------
__global__ void zero_c_kernel() {
    int i = blockIdx.x * blockDim.x + threadIdx.x;   // B*H/4 float4s
    ((float4*)g_c)[i] = make_float4(0.f, 0.f, 0.f, 0.f);
}

__device__ __forceinline__ void split_bf16(float v, __nv_bfloat16& h, __nv_bfloat16& l) {
    h = __float2bfloat16(v);
    l = __float2bfloat16(v - __bfloat162float(h));
}

// x = concat(batch_H, emb[text]) -> bf16 hi/lo.  grid = M1, block = 192
__global__ void convert_x_kernel(const float* __restrict__ bh,
                                 const int* __restrict__ text,
                                 const float* __restrict__ emb) {
    int m = blockIdx.x;
    int k = threadIdx.x * 4;
    float4 v;
    if (k < IN_) v = *(const float4*)(bh + (size_t)m * IN_ + k);
    else         v = *(const float4*)(emb + (size_t)text[m] * NE_ + (k - IN_));
    size_t o = (size_t)m * K1_ + k;
    __nv_bfloat16 h0, h1, h2, h3, l0, l1, l2, l3;
    split_bf16(v.x, h0, l0); split_bf16(v.y, h1, l1);
    split_bf16(v.z, h2, l2); split_bf16(v.w, h3, l3);
    g_xh[o] = h0; g_xh[o+1] = h1; g_xh[o+2] = h2; g_xh[o+3] = h3;
    g_xl[o] = l0; g_xl[o+1] = l1; g_xl[o+2] = l2; g_xl[o+3] = l3;
}

// Weight -> bf16 hi/lo.  grid = R_alloc, block = K/4.  which: 0=Wih 1=Whh 2=Wgen
__global__ void convert_w_kernel(const float* __restrict__ src, int which,
                                 int Rvalid, int K) {
    int r = blockIdx.x;
    int k = threadIdx.x * 4;
    float4 v = make_float4(0.f, 0.f, 0.f, 0.f);
    if (r < Rvalid) v = *(const float4*)(src + (size_t)r * K + k);
    __nv_bfloat16 *dh, *dl;
    if (which == 0)      { dh = g_Wih_h; dl = g_Wih_l; }
    else if (which == 1) { dh = g_Whh_h; dl = g_Whh_l; }
    else                 { dh = g_Wg_h;  dl = g_Wg_l;  }
    size_t o = (size_t)r * K + k;
    __nv_bfloat16 h0, h1, h2, h3, l0, l1, l2, l3;
    split_bf16(v.x, h0, l0); split_bf16(v.y, h1, l1);
    split_bf16(v.z, h2, l2); split_bf16(v.w, h3, l3);
    dh[o] = h0; dh[o+1] = h1; dh[o+2] = h2; dh[o+3] = h3;
    dl[o] = l0; dl[o+1] = l1; dl[o+2] = l2; dl[o+3] = l3;
}

// ---------------------------------------------------------------------------
// Split-bf16 GEMM via mma.sync (HMMA): D[128m x 128n] = sum_k A[m,k]*B[n,k]
//   hi*hi + hi*lo + lo*hi  (fp32 accumulate; lo*lo dropped ~2^-18)
// mode 0: gx    = x @ Wih^T        (K=768) -> g_gx    (+bih)
// mode 1: gates = h(t-1) @ Whh^T   (K=512) -> g_gates (+bhh + gx[:,t,:])
// mode 2: probs = H @ Wgen^T       (K=512) -> outp    (+bg, n<97)
// 8 warps: warp tile 64(m) x 32(n); K-chunk 64.
// ---------------------------------------------------------------------------
__global__ void __launch_bounds__(256)
mma_gemm_kernel(int mode, int t, const float* __restrict__ bias,
                float* __restrict__ outp)
{
    extern __shared__ char dsm[];

    const int tid = threadIdx.x;
    const int wid = tid >> 5;
    const int lid = tid & 31;
    const int wm  = wid & 1;    // 2 m-blocks of 64
    const int wn  = wid >> 1;   // 4 n-blocks of 32
    const int n0  = blockIdx.x * 128;
    const int m0  = blockIdx.y * 128;

    // operand selection
    const __nv_bfloat16 *Ah, *Al, *Bh, *Bl;
    long lda, ldb;
    int K;
    if (mode == 0) {
        Ah = g_xh; Al = g_xl; lda = K1_;
        Bh = g_Wih_h; Bl = g_Wih_l; ldb = K1_; K = K1_;
    } else if (mode == 1) {
        Ah = g_Hh + (size_t)(t - 1) * H_;   // row b -> (b*T + t-1)*H
        Al = g_Hl + (size_t)(t - 1) * H_;
        lda = (long)T_ * H_;
        Bh = g_Whh_h; Bl = g_Whh_l; ldb = H_; K = H_;
    } else {
        Ah = g_Hh; Al = g_Hl; lda = H_;
        Bh = g_Wg_h; Bl = g_Wg_l; ldb = H_; K = H_;
    }

    uint32_t raw  = smem_u32(dsm);
    uint32_t base = (raw + 127) & ~127u;
    char* pAh = dsm + (base - raw);
    char* pAl = pAh + 16384;
    char* pBh = pAh + 32768;
    char* pBl = pAh + 49152;
    const uint32_t aAh = base, aAl = base + 16384;
    const uint32_t aBh = base + 32768, aBl = base + 49152;

    float acc[4][4][4];
#pragma unroll
    for (int mt = 0; mt < 4; mt++)
#pragma unroll
        for (int nt = 0; nt < 4; nt++)
#pragma unroll
            for (int r = 0; r < 4; r++) acc[mt][nt][r] = 0.0f;

    // per-lane ldmatrix address components
    const int a_r  = lid & 15;          // A: row within m16
    const int a_kh = lid >> 4;          // A: k half-block (0/1)
    const int b_r  = (lid & 7) + ((lid & 16) ? 8 : 0);  // B: n within 16
    const int b_kh = (lid >> 3) & 1;                     // B: k half-block

    const int nchunks = K >> 6;   // 64-k chunks
    for (int ch = 0; ch < nchunks; ch++) {
        const int k0 = ch * 64;
        // fill 4 tiles, 128 rows x 128B each, XOR-swizzled 16B chunks
#pragma unroll
        for (int i = tid; i < 1024; i += 256) {
            int r = i >> 3, u = i & 7;
            uint32_t sw = (r << 7) + ((u ^ (r & 7)) << 4);
            *(uint4*)(pAh + sw) = *((const uint4*)(Ah + (size_t)(m0 + r) * lda + k0) + u);
            *(uint4*)(pAl + sw) = *((const uint4*)(Al + (size_t)(m0 + r) * lda + k0) + u);
            *(uint4*)(pBh + sw) = *((const uint4*)(Bh + (size_t)(n0 + r) * ldb + k0) + u);
            *(uint4*)(pBl + sw) = *((const uint4*)(Bl + (size_t)(n0 + r) * ldb + k0) + u);
        }
        __syncthreads();

#pragma unroll
        for (int ks = 0; ks < 4; ks++) {
            uint32_t ah[4][4], al[4][4], bh[2][4], bl[2][4];
#pragma unroll
            for (int mt = 0; mt < 4; mt++) {
                int row = wm * 64 + mt * 16 + a_r;
                int kb  = ks * 2 + a_kh;
                uint32_t off = (row << 7) + ((kb ^ (row & 7)) << 4);
                ldmx4(ah[mt], aAh + off);
                ldmx4(al[mt], aAl + off);
            }
#pragma unroll
            for (int p = 0; p < 2; p++) {
                int row = wn * 32 + p * 16 + b_r;
                int kb  = ks * 2 + b_kh;
                uint32_t off = (row << 7) + ((kb ^ (row & 7)) << 4);
                ldmx4(bh[p], aBh + off);
                ldmx4(bl[p], aBl + off);
            }
#pragma unroll
            for (int mt = 0; mt < 4; mt++)
#pragma unroll
                for (int nt = 0; nt < 4; nt++) {
                    int p = nt >> 1, o = (nt & 1) * 2;
                    mma_bf16(acc[mt][nt], ah[mt], bh[p][o], bh[p][o + 1]);
                    mma_bf16(acc[mt][nt], ah[mt], bl[p][o], bl[p][o + 1]);
                    mma_bf16(acc[mt][nt], al[mt], bh[p][o], bh[p][o + 1]);
                }
        }
        __syncthreads();
    }

    // Epilogue: D frags -> global (thread t: rows qr, qr+8; cols 2*qc, +1)
    const int qr = lid >> 2, qc = lid & 3;
#pragma unroll
    for (int mt = 0; mt < 4; mt++)
#pragma unroll
        for (int nt = 0; nt < 4; nt++)
#pragma unroll
            for (int half = 0; half < 2; half++) {
                int m = m0 + wm * 64 + mt * 16 + qr + half * 8;
                int n = n0 + wn * 32 + nt * 8 + qc * 2;
                float v0 = acc[mt][nt][half * 2];
                float v1 = acc[mt][nt][half * 2 + 1];
                if (mode == 2) {
                    if (n < NC_)     outp[(size_t)m * NC_ + n]     = v0 + bias[n];
                    if (n + 1 < NC_) outp[(size_t)m * NC_ + n + 1] = v1 + bias[n + 1];
                } else if (mode == 0) {
                    float2 o2 = make_float2(v0 + bias[n], v1 + bias[n + 1]);
                    *(float2*)(g_gx + (size_t)m * G_ + n) = o2;
                } else {
                    float2 gx = *(const float2*)(g_gx + ((size_t)m * T_ + t) * G_ + n);
                    float2 o2 = make_float2(v0 + bias[n] + gx.x,
                                            v1 + bias[n + 1] + gx.y);
                    *(float2*)(g_gates + (size_t)m * G_ + n) = o2;
                }
            }
}

// ---------------------------------------------------------------------------
// LSTM pointwise: gates -> (h, c); writes fp32 hiddens + bf16 hi/lo copy
// ---------------------------------------------------------------------------
__global__ void lstm_pointwise(float* __restrict__ out_hid,
                               const float* __restrict__ bhh, int t)
{
    int idx = blockIdx.x * blockDim.x + threadIdx.x;
    int b = idx >> 9;
    int j = idx & 511;

    float gi, gf, gg, go;
    if (t == 0) {
        const float* gr = g_gx + (size_t)b * T_ * G_;   // row b*T + 0 (h=0)
        gi = gr[j]        + bhh[j];
        gf = gr[j +   H_] + bhh[j +   H_];
        gg = gr[j + 2*H_] + bhh[j + 2*H_];
        go = gr[j + 3*H_] + bhh[j + 3*H_];
    } else {
        const float* gr = g_gates + (size_t)b * G_;     // bhh + gx already added
        gi = gr[j]; gf = gr[j + H_]; gg = gr[j + 2*H_]; go = gr[j + 3*H_];
    }

    float i_ = 1.0f / (1.0f + expf(-gi));
    float f_ = 1.0f / (1.0f + expf(-gf));
    float g_ = tanhf(gg);
    float o_ = 1.0f / (1.0f + expf(-go));

    float c = f_ * g_c[idx] + i_ * g_;
    float h = o_ * tanhf(c);
    g_c[idx] = c;

    size_t o = ((size_t)b * T_ + t) * H_ + j;
    out_hid[o] = h;
    __nv_bfloat16 hh, hl;
    split_bf16(h, hh, hl);
    g_Hh[o] = hh;
    g_Hl[o] = hl;
}

// ---------------------------------------------------------------------------
// Launch graph: zero -> converts -> gx GEMM -> 26 steps -> probs GEMM
// d_out = [probs (B*T*97) | output_hiddens (B*T*512)]
// ---------------------------------------------------------------------------
extern "C" void kernel_launch(void* const* d_in, const int* in_sizes, int n_in,
                              void* d_out, int out_size)
{
    const float* bh   = (const float*)d_in[0];
    const int*   text = (const int*)  d_in[1];
    const float* emb  = (const float*)d_in[2];
    const float* Wih  = (const float*)d_in[3];
    const float* Whh  = (const float*)d_in[4];
    const float* bih  = (const float*)d_in[5];
    const float* bhh  = (const float*)d_in[6];
    const float* Wg   = (const float*)d_in[7];
    const float* bg   = (const float*)d_in[8];

    float* probs = (float*)d_out;                     // [M1, 97]
    float* hid   = probs + (size_t)M1_ * NC_;         // [M1, 512]

    (void)in_sizes; (void)n_in; (void)out_size;

    cudaFuncSetAttribute((const void*)mma_gemm_kernel,
                         cudaFuncAttributeMaxDynamicSharedMemorySize, SMEM_DYN);

    zero_c_kernel<<<(B_ * H_ / 4) / 256, 256>>>();
    convert_x_kernel<<<M1_, K1_ / 4>>>(bh, text, emb);
    convert_w_kernel<<<G_,  K1_ / 4>>>(Wih, 0, G_,  K1_);
    convert_w_kernel<<<G_,  H_  / 4>>>(Whh, 1, G_,  H_);
    convert_w_kernel<<<128, H_  / 4>>>(Wg,  2, NC_, H_);

    // gx: M=106496 x N=2048, K=768.  n-tiles fastest => A tile L2-resident.
    mma_gemm_kernel<<<dim3(16, 832), 256, SMEM_DYN>>>(0, 0, bih, nullptr);

    lstm_pointwise<<<(B_ * H_) / 256, 256>>>(hid, bhh, 0);   // t=0: h=0 path
    for (int t = 1; t < T_; t++) {
        mma_gemm_kernel<<<dim3(16, 32), 256, SMEM_DYN>>>(1, t, bhh, nullptr);
        lstm_pointwise<<<(B_ * H_) / 256, 256>>>(hid, bhh, t);
    }

    // probs: N=97 padded to one 128-tile
    mma_gemm_kernel<<<dim3(1, 832), 256, SMEM_DYN>>>(2, 0, bg, probs);
}

// round 8
// speedup vs baseline: 2.3508x; 1.2095x over previous
#include <cuda_runtime.h>
#include <cuda_bf16.h>
#include <stdint.h>
#include <math.h>

// Problem constants
#define B_   4096
#define T_   26
#define IN_  512
#define H_   512
#define NC_  97
#define NE_  256
#define K1_  (IN_ + NE_)   // 768
#define G_   (4 * H_)      // 2048
#define M1_  (B_ * T_)     // 106496

// 2 pipeline stages x 4 tiles (A_hi, A_lo, B_hi, B_lo) x 16KB
#define STAGE_BYTES 65536
#define SMEM_DYN (2 * STAGE_BYTES + 128)

// ---------------------------------------------------------------------------
// Scratch (device globals: no allocation allowed anywhere)
// ---------------------------------------------------------------------------
// g_gx is stored in PERMUTED gate order: col n holds gate (n&3) of unit (n>>2)
// (i.e. [i0,f0,g0,o0, i1,f1,g1,o1, ...]).  W_ih/W_hh rows permuted to match.
__device__ float g_gx[(size_t)M1_ * G_];
__device__ float g_c[B_ * H_];                 // cell state
__device__ __nv_bfloat16 g_xh[(size_t)M1_ * K1_];  // x split hi/lo
__device__ __nv_bfloat16 g_xl[(size_t)M1_ * K1_];
__device__ __nv_bfloat16 g_Hh[(size_t)M1_ * H_];   // hiddens hi/lo [b*T+t, H]
__device__ __nv_bfloat16 g_Hl[(size_t)M1_ * H_];
__device__ __nv_bfloat16 g_Wih_h[G_ * K1_];
__device__ __nv_bfloat16 g_Wih_l[G_ * K1_];
__device__ __nv_bfloat16 g_Whh_h[G_ * H_];
__device__ __nv_bfloat16 g_Whh_l[G_ * H_];
__device__ __nv_bfloat16 g_Wg_h[128 * H_];     // W_gen padded to 128 rows
__device__ __nv_bfloat16 g_Wg_l[128 * H_];

// ---------------------------------------------------------------------------
// PTX helpers (compute_103-safe: ldmatrix + mma.sync + cp.async)
// ---------------------------------------------------------------------------
__device__ __forceinline__ uint32_t smem_u32(const void* p) {
    uint32_t a;
    asm("{ .reg .u64 t; cvta.to.shared.u64 t, %1; cvt.u32.u64 %0, t; }"
        : "=r"(a) : "l"(p));
    return a;
}

__device__ __forceinline__ void ldmx4(uint32_t* r, uint32_t addr) {
    asm volatile("ldmatrix.sync.aligned.m8n8.x4.shared.b16 {%0,%1,%2,%3}, [%4];"
                 : "=r"(r[0]), "=r"(r[1]), "=r"(r[2]), "=r"(r[3]) : "r"(addr));
}

__device__ __forceinline__ void mma_bf16(float* d, const uint32_t* a,
                                         uint32_t b0, uint32_t b1) {
    asm volatile(
        "mma.sync.aligned.m16n8k16.row.col.f32.bf16.bf16.f32 "
        "{%0,%1,%2,%3}, {%4,%5,%6,%7}, {%8,%9}, {%0,%1,%2,%3};"
        : "+f"(d[0]), "+f"(d[1]), "+f"(d[2]), "+f"(d[3])
        : "r"(a[0]), "r"(a[1]), "r"(a[2]), "r"(a[3]), "r"(b0), "r"(b1));
}

__device__ __forceinline__ void cp16(uint32_t s, const void* g) {
    asm volatile("cp.async.cg.shared.global [%0], [%1], 16;"
                 :: "r"(s), "l"(g) : "memory");
}
__device__ __forceinline__ void cp_commit() {
    asm volatile("cp.async.commit_group;" ::: "memory");
}
template <int N>
__device__ __forceinline__ void cp_wait() {
    asm volatile("cp.async.wait_group %0;" :: "n"(N) : "memory");
}

// ---------------------------------------------------------------------------
// Small prep kernels
// ---------------------------------------------------------------------------
__global__ void zero_c_kernel() {
    int i = blockIdx.x * blockDim.x + threadIdx.x;
    ((float4*)g_c)[i] = make_float4(0.f, 0.f, 0.f, 0.f);
}

__device__ __forceinline__ void split_bf16(float v, __nv_bfloat16& h, __nv_bfloat16& l) {
    h = __float2bfloat16(v);
    l = __float2bfloat16(v - __bfloat162float(h));
}

// x = concat(batch_H, emb[text]) -> bf16 hi/lo.  grid = M1, block = 192
__global__ void convert_x_kernel(const float* __restrict__ bh,
                                 const int* __restrict__ text,
                                 const float* __restrict__ emb) {
    int m = blockIdx.x;
    int k = threadIdx.x * 4;
    float4 v;
    if (k < IN_) v = *(const float4*)(bh + (size_t)m * IN_ + k);
    else         v = *(const float4*)(emb + (size_t)text[m] * NE_ + (k - IN_));
    size_t o = (size_t)m * K1_ + k;
    __nv_bfloat16 h0, h1, h2, h3, l0, l1, l2, l3;
    split_bf16(v.x, h0, l0); split_bf16(v.y, h1, l1);
    split_bf16(v.z, h2, l2); split_bf16(v.w, h3, l3);
    g_xh[o] = h0; g_xh[o+1] = h1; g_xh[o+2] = h2; g_xh[o+3] = h3;
    g_xl[o] = l0; g_xl[o+1] = l1; g_xl[o+2] = l2; g_xl[o+3] = l3;
}

// Weight -> bf16 hi/lo.  which: 0=Wih 1=Whh (gate-permuted) 2=Wgen (padded)
__global__ void convert_w_kernel(const float* __restrict__ src, int which,
                                 int Rvalid, int K) {
    int r = blockIdx.x;                       // destination row
    int k = threadIdx.x * 4;
    int sr = (which < 2) ? ((r & 3) * H_ + (r >> 2)) : r;   // gate permutation
    float4 v = make_float4(0.f, 0.f, 0.f, 0.f);
    if (sr < Rvalid) v = *(const float4*)(src + (size_t)sr * K + k);
    __nv_bfloat16 *dh, *dl;
    if (which == 0)      { dh = g_Wih_h; dl = g_Wih_l; }
    else if (which == 1) { dh = g_Whh_h; dl = g_Whh_l; }
    else                 { dh = g_Wg_h;  dl = g_Wg_l;  }
    size_t o = (size_t)r * K + k;
    __nv_bfloat16 h0, h1, h2, h3, l0, l1, l2, l3;
    split_bf16(v.x, h0, l0); split_bf16(v.y, h1, l1);
    split_bf16(v.z, h2, l2); split_bf16(v.w, h3, l3);
    dh[o] = h0; dh[o+1] = h1; dh[o+2] = h2; dh[o+3] = h3;
    dl[o] = l0; dl[o+1] = l1; dl[o+2] = l2; dl[o+3] = l3;
}

// ---------------------------------------------------------------------------
// Split-bf16 GEMM via mma.sync, 2-stage cp.async pipeline.
//   hi*hi + hi*lo + lo*hi  (fp32 accumulate)
// mode 0: gx    = x @ Wih^T (perm)  (K=768) -> g_gx (+bih perm)
// mode 1: gates = h(t-1) @ Whh^T (perm), then FUSED LSTM pointwise epilogue
// mode 2: probs = H @ Wgen^T        (K=512) -> outp (+bg, n<97)
// 8 warps: warp tile 64(m) x 32(n); K-chunk 64.
// ---------------------------------------------------------------------------
__global__ void __launch_bounds__(256)
mma_gemm_kernel(int mode, int t, const float* __restrict__ bias,
                float* __restrict__ outp)
{
    extern __shared__ char dsm[];

    const int tid = threadIdx.x;
    const int wid = tid >> 5;
    const int lid = tid & 31;
    const int wm  = wid & 1;    // 2 m-blocks of 64
    const int wn  = wid >> 1;   // 4 n-blocks of 32
    const int n0  = blockIdx.x * 128;
    const int m0  = blockIdx.y * 128;

    const __nv_bfloat16 *Ah, *Al, *Bh, *Bl;
    long lda, ldb;
    int K;
    if (mode == 0) {
        Ah = g_xh; Al = g_xl; lda = K1_;
        Bh = g_Wih_h; Bl = g_Wih_l; ldb = K1_; K = K1_;
    } else if (mode == 1) {
        Ah = g_Hh + (size_t)(t - 1) * H_;   // row b -> (b*T + t-1)*H
        Al = g_Hl + (size_t)(t - 1) * H_;
        lda = (long)T_ * H_;
        Bh = g_Whh_h; Bl = g_Whh_l; ldb = H_; K = H_;
    } else {
        Ah = g_Hh; Al = g_Hl; lda = H_;
        Bh = g_Wg_h; Bl = g_Wg_l; ldb = H_; K = H_;
    }

    uint32_t raw  = smem_u32(dsm);
    uint32_t base = (raw + 127) & ~127u;
    float* stage_f = (float*)(dsm + (base - raw));   // epilogue stage (reuses pipe smem)
    const uint32_t stg[2] = { base, base + STAGE_BYTES };

    float acc[4][4][4];
#pragma unroll
    for (int mt = 0; mt < 4; mt++)
#pragma unroll
        for (int nt = 0; nt < 4; nt++)
#pragma unroll
            for (int r = 0; r < 4; r++) acc[mt][nt][r] = 0.0f;

    // per-lane ldmatrix address components
    const int a_r  = lid & 15;
    const int a_kh = lid >> 4;
    const int b_r  = (lid & 7) + ((lid & 16) ? 8 : 0);
    const int b_kh = (lid >> 3) & 1;

    const int nchunks = K >> 6;

    // ---- async stage loader: 4 tiles x (128 rows x 128B), XOR-swizzled ----
    auto load_stage = [&](int ch, uint32_t sb) {
        const int k0 = ch * 64;
#pragma unroll
        for (int i = tid; i < 1024; i += 256) {
            int r = i >> 3, u = i & 7;
            uint32_t sw = (r << 7) + ((u ^ (r & 7)) << 4);
            size_t ao = (size_t)(m0 + r) * lda + k0 + u * 8;
            size_t bo = (size_t)(n0 + r) * ldb + k0 + u * 8;
            cp16(sb + sw,          Ah + ao);
            cp16(sb + 16384 + sw,  Al + ao);
            cp16(sb + 32768 + sw,  Bh + bo);
            cp16(sb + 49152 + sw,  Bl + bo);
        }
    };

    load_stage(0, stg[0]);
    cp_commit();

    for (int ch = 0; ch < nchunks; ch++) {
        if (ch + 1 < nchunks) load_stage(ch + 1, stg[(ch + 1) & 1]);
        cp_commit();
        cp_wait<1>();
        __syncthreads();

        const uint32_t sb  = stg[ch & 1];
        const uint32_t aAh = sb, aAl = sb + 16384;
        const uint32_t aBh = sb + 32768, aBl = sb + 49152;

#pragma unroll
        for (int ks = 0; ks < 4; ks++) {
            uint32_t ah[4][4], al[4][4], bh[2][4], bl[2][4];
#pragma unroll
            for (int mt = 0; mt < 4; mt++) {
                int row = wm * 64 + mt * 16 + a_r;
                int kb  = ks * 2 + a_kh;
                uint32_t off = (row << 7) + ((kb ^ (row & 7)) << 4);
                ldmx4(ah[mt], aAh + off);
                ldmx4(al[mt], aAl + off);
            }
#pragma unroll
            for (int p = 0; p < 2; p++) {
                int row = wn * 32 + p * 16 + b_r;
                int kb  = ks * 2 + b_kh;
                uint32_t off = (row << 7) + ((kb ^ (row & 7)) << 4);
                ldmx4(bh[p], aBh + off);
                ldmx4(bl[p], aBl + off);
            }
#pragma unroll
            for (int mt = 0; mt < 4; mt++)
#pragma unroll
                for (int nt = 0; nt < 4; nt++) {
                    int p = nt >> 1, o = (nt & 1) * 2;
                    mma_bf16(acc[mt][nt], ah[mt], bh[p][o], bh[p][o + 1]);
                    mma_bf16(acc[mt][nt], ah[mt], bl[p][o], bl[p][o + 1]);
                    mma_bf16(acc[mt][nt], al[mt], bh[p][o], bh[p][o + 1]);
                }
        }
        __syncthreads();
    }

    const int qr = lid >> 2, qc = lid & 3;

    if (mode == 1) {
        // ---- fused LSTM epilogue: stage raw acc, then pointwise ----
#pragma unroll
        for (int mt = 0; mt < 4; mt++)
#pragma unroll
            for (int nt = 0; nt < 4; nt++)
#pragma unroll
                for (int half = 0; half < 2; half++) {
                    int r = wm * 64 + mt * 16 + qr + half * 8;
                    int n = wn * 32 + nt * 8 + qc * 2;
                    stage_f[r * 132 + n]     = acc[mt][nt][half * 2];
                    stage_f[r * 132 + n + 1] = acc[mt][nt][half * 2 + 1];
                }
        __syncthreads();

        // pointwise: tile cols = 32 hidden units x 4 gates (permuted layout)
        const int j0 = n0 >> 2;   // first hidden unit of this n-tile
#pragma unroll
        for (int i = tid; i < 4096; i += 256) {
            int r  = i >> 5;       // warp-uniform row
            int jj = i & 31;
            int b  = m0 + r;
            int j  = j0 + jj;
            float4 a4 = *(const float4*)&stage_f[r * 132 + jj * 4];
            const float4 gx = *(const float4*)(g_gx + ((size_t)b * T_ + t) * G_ + n0 + jj * 4);
            float gi = a4.x + gx.x + bias[j];
            float gf = a4.y + gx.y + bias[j +     H_];
            float gg = a4.z + gx.z + bias[j + 2 * H_];
            float go = a4.w + gx.w + bias[j + 3 * H_];

            float i_ = 1.0f / (1.0f + expf(-gi));
            float f_ = 1.0f / (1.0f + expf(-gf));
            float g_ = tanhf(gg);
            float o_ = 1.0f / (1.0f + expf(-go));

            int idx = b * H_ + j;
            float c = f_ * g_c[idx] + i_ * g_;
            float h = o_ * tanhf(c);
            g_c[idx] = c;

            size_t oo = ((size_t)b * T_ + t) * H_ + j;
            outp[oo] = h;                         // fp32 hiddens (output)
            __nv_bfloat16 hh, hl;
            split_bf16(h, hh, hl);
            g_Hh[oo] = hh;
            g_Hl[oo] = hl;
        }
        return;
    }

    // ---- modes 0 / 2: direct fragment store ----
#pragma unroll
    for (int mt = 0; mt < 4; mt++)
#pragma unroll
        for (int nt = 0; nt < 4; nt++)
#pragma unroll
            for (int half = 0; half < 2; half++) {
                int m = m0 + wm * 64 + mt * 16 + qr + half * 8;
                int n = n0 + wn * 32 + nt * 8 + qc * 2;
                float v0 = acc[mt][nt][half * 2];
                float v1 = acc[mt][nt][half * 2 + 1];
                if (mode == 2) {
                    if (n < NC_)     outp[(size_t)m * NC_ + n]     = v0 + bias[n];
                    if (n + 1 < NC_) outp[(size_t)m * NC_ + n + 1] = v1 + bias[n + 1];
                } else {
                    // permuted bias: dest col n holds gate (n&3) of unit (n>>2)
                    float b0 = bias[(n & 3) * H_ + (n >> 2)];
                    float b1 = bias[((n + 1) & 3) * H_ + ((n + 1) >> 2)];
                    *(float2*)(g_gx + (size_t)m * G_ + n) = make_float2(v0 + b0, v1 + b1);
                }
            }
}

// ---------------------------------------------------------------------------
// t = 0 step: h = 0, so gates = gx (permuted, bih included) + bhh
// ---------------------------------------------------------------------------
__global__ void lstm_t0(float* __restrict__ out_hid, const float* __restrict__ bhh)
{
    int i = blockIdx.x * blockDim.x + threadIdx.x;   // B*H
    int b = i >> 9;
    int j = i & 511;

    const float4 g4 = *(const float4*)(g_gx + (size_t)b * T_ * G_ + 4 * j);
    float gi = g4.x + bhh[j];
    float gf = g4.y + bhh[j +     H_];
    float gg = g4.z + bhh[j + 2 * H_];
    float go = g4.w + bhh[j + 3 * H_];

    float i_ = 1.0f / (1.0f + expf(-gi));
    float f_ = 1.0f / (1.0f + expf(-gf));
    float g_ = tanhf(gg);
    float o_ = 1.0f / (1.0f + expf(-go));

    float c = i_ * g_;          // c_prev = 0
    float h = o_ * tanhf(c);
    g_c[i] = c;

    size_t o = (size_t)b * T_ * H_ + j;   // t = 0
    out_hid[o] = h;
    __nv_bfloat16 hh, hl;
    split_bf16(h, hh, hl);
    g_Hh[o] = hh;
    g_Hl[o] = hl;
}

// ---------------------------------------------------------------------------
// Launch: zero -> converts -> gx GEMM -> t0 -> 25 fused steps -> probs GEMM
// d_out = [probs (B*T*97) | output_hiddens (B*T*512)]
// ---------------------------------------------------------------------------
extern "C" void kernel_launch(void* const* d_in, const int* in_sizes, int n_in,
                              void* d_out, int out_size)
{
    const float* bh   = (const float*)d_in[0];
    const int*   text = (const int*)  d_in[1];
    const float* emb  = (const float*)d_in[2];
    const float* Wih  = (const float*)d_in[3];
    const float* Whh  = (const float*)d_in[4];
    const float* bih  = (const float*)d_in[5];
    const float* bhh  = (const float*)d_in[6];
    const float* Wg   = (const float*)d_in[7];
    const float* bg   = (const float*)d_in[8];

    float* probs = (float*)d_out;                     // [M1, 97]
    float* hid   = probs + (size_t)M1_ * NC_;         // [M1, 512]

    (void)in_sizes; (void)n_in; (void)out_size;

    cudaFuncSetAttribute((const void*)mma_gemm_kernel,
                         cudaFuncAttributeMaxDynamicSharedMemorySize, SMEM_DYN);

    zero_c_kernel<<<(B_ * H_ / 4) / 256, 256>>>();
    convert_x_kernel<<<M1_, K1_ / 4>>>(bh, text, emb);
    convert_w_kernel<<<G_,  K1_ / 4>>>(Wih, 0, G_,  K1_);
    convert_w_kernel<<<G_,  H_  / 4>>>(Whh, 1, G_,  H_);
    convert_w_kernel<<<128, H_  / 4>>>(Wg,  2, NC_, H_);

    // gx: M=106496 x N=2048, K=768.  n-tiles fastest => A tile L2-resident.
    mma_gemm_kernel<<<dim3(16, 832), 256, SMEM_DYN>>>(0, 0, bih, nullptr);

    lstm_t0<<<(B_ * H_) / 256, 256>>>(hid, bhh);
    for (int t = 1; t < T_; t++)
        mma_gemm_kernel<<<dim3(16, 32), 256, SMEM_DYN>>>(1, t, bhh, hid);

    // probs: N=97 padded to one 128-tile
    mma_gemm_kernel<<<dim3(1, 832), 256, SMEM_DYN>>>(2, 0, bg, probs);
}

// round 9
// speedup vs baseline: 2.9871x; 1.2707x over previous
#include <cuda_runtime.h>
#include <cuda_fp16.h>
#include <stdint.h>
#include <math.h>

// Problem constants
#define B_   4096
#define T_   26
#define IN_  512
#define H_   512
#define NC_  97
#define NE_  256
#define K1_  (IN_ + NE_)   // 768
#define G_   (4 * H_)      // 2048
#define M1_  (B_ * T_)     // 106496

// Pipeline: 3 stages x 3 tiles (A, B_hi, B_lo) x 16KB
#define TILE_BYTES  16384
#define STAGE_BYTES (3 * TILE_BYTES)
#define NSTAGES     3
#define SMEM_DYN    (NSTAGES * STAGE_BYTES + 128)

// ---------------------------------------------------------------------------
// Scratch (device globals: no allocation allowed anywhere)
// ---------------------------------------------------------------------------
// g_gx stored in PERMUTED gate order: col n holds gate (n&3) of unit (n>>2).
__device__ float g_gx[(size_t)M1_ * G_];
__device__ float g_c[B_ * H_];                    // cell state
__device__ __half g_x[(size_t)M1_ * K1_];         // x (concat) fp16
__device__ __half g_H[(size_t)M1_ * H_];          // hiddens fp16 [b*T+t, H]
__device__ __half g_Wih_h[G_ * K1_];              // weights fp16 hi/lo (2-term)
__device__ __half g_Wih_l[G_ * K1_];
__device__ __half g_Whh_h[G_ * H_];
__device__ __half g_Whh_l[G_ * H_];
__device__ __half g_Wg_h[128 * H_];               // W_gen padded to 128 rows
__device__ __half g_Wg_l[128 * H_];

// ---------------------------------------------------------------------------
// PTX helpers (compute_103-safe: ldmatrix + mma.sync + cp.async)
// ---------------------------------------------------------------------------
__device__ __forceinline__ uint32_t smem_u32(const void* p) {
    uint32_t a;
    asm("{ .reg .u64 t; cvta.to.shared.u64 t, %1; cvt.u32.u64 %0, t; }"
        : "=r"(a) : "l"(p));
    return a;
}

__device__ __forceinline__ void ldmx4(uint32_t* r, uint32_t addr) {
    asm volatile("ldmatrix.sync.aligned.m8n8.x4.shared.b16 {%0,%1,%2,%3}, [%4];"
                 : "=r"(r[0]), "=r"(r[1]), "=r"(r[2]), "=r"(r[3]) : "r"(addr));
}

__device__ __forceinline__ void mma_f16(float* d, const uint32_t* a,
                                        uint32_t b0, uint32_t b1) {
    asm volatile(
        "mma.sync.aligned.m16n8k16.row.col.f32.f16.f16.f32 "
        "{%0,%1,%2,%3}, {%4,%5,%6,%7}, {%8,%9}, {%0,%1,%2,%3};"
        : "+f"(d[0]), "+f"(d[1]), "+f"(d[2]), "+f"(d[3])
        : "r"(a[0]), "r"(a[1]), "r"(a[2]), "r"(a[3]), "r"(b0), "r"(b1));
}

__device__ __forceinline__ void cp16(uint32_t s, const void* g) {
    asm volatile("cp.async.cg.shared.global [%0], [%1], 16;"
                 :: "r"(s), "l"(g) : "memory");
}
__device__ __forceinline__ void cp_commit() {
    asm volatile("cp.async.commit_group;" ::: "memory");
}
template <int N>
__device__ __forceinline__ void cp_wait() {
    asm volatile("cp.async.wait_group %0;" :: "n"(N) : "memory");
}

// ---------------------------------------------------------------------------
// Small prep kernels
// ---------------------------------------------------------------------------
__global__ void zero_c_kernel() {
    int i = blockIdx.x * blockDim.x + threadIdx.x;
    ((float4*)g_c)[i] = make_float4(0.f, 0.f, 0.f, 0.f);
}

__device__ __forceinline__ void split_h16(float v, __half& h, __half& l) {
    h = __float2half_rn(v);
    l = __float2half_rn(v - __half2float(h));
}

// x = concat(batch_H, emb[text]) -> fp16.  grid = M1, block = 192
__global__ void convert_x_kernel(const float* __restrict__ bh,
                                 const int* __restrict__ text,
                                 const float* __restrict__ emb) {
    int m = blockIdx.x;
    int k = threadIdx.x * 4;
    float4 v;
    if (k < IN_) v = *(const float4*)(bh + (size_t)m * IN_ + k);
    else         v = *(const float4*)(emb + (size_t)text[m] * NE_ + (k - IN_));
    size_t o = (size_t)m * K1_ + k;
    g_x[o]   = __float2half_rn(v.x);
    g_x[o+1] = __float2half_rn(v.y);
    g_x[o+2] = __float2half_rn(v.z);
    g_x[o+3] = __float2half_rn(v.w);
}

// Weight -> fp16 hi/lo.  which: 0=Wih 1=Whh (gate-permuted) 2=Wgen (padded)
__global__ void convert_w_kernel(const float* __restrict__ src, int which,
                                 int Rvalid, int K) {
    int r = blockIdx.x;                       // destination row
    int k = threadIdx.x * 4;
    int sr = (which < 2) ? ((r & 3) * H_ + (r >> 2)) : r;   // gate permutation
    float4 v = make_float4(0.f, 0.f, 0.f, 0.f);
    if (sr < Rvalid) v = *(const float4*)(src + (size_t)sr * K + k);
    __half *dh, *dl;
    if (which == 0)      { dh = g_Wih_h; dl = g_Wih_l; }
    else if (which == 1) { dh = g_Whh_h; dl = g_Whh_l; }
    else                 { dh = g_Wg_h;  dl = g_Wg_l;  }
    size_t o = (size_t)r * K + k;
    __half h0, h1, h2, h3, l0, l1, l2, l3;
    split_h16(v.x, h0, l0); split_h16(v.y, h1, l1);
    split_h16(v.z, h2, l2); split_h16(v.w, h3, l3);
    dh[o] = h0; dh[o+1] = h1; dh[o+2] = h2; dh[o+3] = h3;
    dl[o] = l0; dl[o+1] = l1; dl[o+2] = l2; dl[o+3] = l3;
}

// ---------------------------------------------------------------------------
// fp16 GEMM via mma.sync, 3-stage cp.async pipeline.
//   acc += A * (W_hi + W_lo)   (fp32 accumulate; A single fp16)
// mode 0: gx    = x @ Wih^T (perm)  (K=768) -> g_gx (+bih perm)
// mode 1: gates = h(t-1) @ Whh^T (perm), FUSED LSTM pointwise epilogue
// mode 2: probs = H @ Wgen^T        (K=512) -> outp (+bg, n<97)
// 8 warps: warp tile 64(m) x 32(n); K-chunk 64.
// ---------------------------------------------------------------------------
__global__ void __launch_bounds__(256)
mma_gemm_kernel(int mode, int t, const float* __restrict__ bias,
                float* __restrict__ outp)
{
    extern __shared__ char dsm[];

    const int tid = threadIdx.x;
    const int wid = tid >> 5;
    const int lid = tid & 31;
    const int wm  = wid & 1;    // 2 m-blocks of 64
    const int wn  = wid >> 1;   // 4 n-blocks of 32
    const int n0  = blockIdx.x * 128;
    const int m0  = blockIdx.y * 128;

    const __half *A, *Bh, *Bl;
    long lda, ldb;
    int K;
    if (mode == 0) {
        A = g_x; lda = K1_;
        Bh = g_Wih_h; Bl = g_Wih_l; ldb = K1_; K = K1_;
    } else if (mode == 1) {
        A = g_H + (size_t)(t - 1) * H_;     // row b -> (b*T + t-1)*H
        lda = (long)T_ * H_;
        Bh = g_Whh_h; Bl = g_Whh_l; ldb = H_; K = H_;
    } else {
        A = g_H; lda = H_;
        Bh = g_Wg_h; Bl = g_Wg_l; ldb = H_; K = H_;
    }

    uint32_t raw  = smem_u32(dsm);
    uint32_t base = (raw + 127) & ~127u;
    float* stage_f = (float*)(dsm + (base - raw));   // epilogue stage (reuse)
    uint32_t stg[NSTAGES];
#pragma unroll
    for (int s = 0; s < NSTAGES; s++) stg[s] = base + s * STAGE_BYTES;

    float acc[4][4][4];
#pragma unroll
    for (int mt = 0; mt < 4; mt++)
#pragma unroll
        for (int nt = 0; nt < 4; nt++)
#pragma unroll
            for (int r = 0; r < 4; r++) acc[mt][nt][r] = 0.0f;

    // per-lane ldmatrix address components
    const int a_r  = lid & 15;
    const int a_kh = lid >> 4;
    const int b_r  = (lid & 7) + ((lid & 16) ? 8 : 0);
    const int b_kh = (lid >> 3) & 1;

    const int nchunks = K >> 6;

    // ---- async stage loader: 3 tiles x (128 rows x 128B), XOR-swizzled ----
    auto load_stage = [&](int ch, uint32_t sb) {
        const int k0 = ch * 64;
#pragma unroll
        for (int i = tid; i < 1024; i += 256) {
            int r = i >> 3, u = i & 7;
            uint32_t sw = (r << 7) + ((u ^ (r & 7)) << 4);
            size_t ao = (size_t)(m0 + r) * lda + k0 + u * 8;
            size_t bo = (size_t)(n0 + r) * ldb + k0 + u * 8;
            cp16(sb + sw,                   A + ao);
            cp16(sb + TILE_BYTES + sw,      Bh + bo);
            cp16(sb + 2 * TILE_BYTES + sw,  Bl + bo);
        }
    };

    // prologue: stages 0, 1 in flight
#pragma unroll
    for (int s = 0; s < NSTAGES - 1; s++) {
        if (s < nchunks) load_stage(s, stg[s]);
        cp_commit();
    }

    for (int ch = 0; ch < nchunks; ch++) {
        if (ch + NSTAGES - 1 < nchunks)
            load_stage(ch + NSTAGES - 1, stg[(ch + NSTAGES - 1) % NSTAGES]);
        cp_commit();
        cp_wait<NSTAGES - 1>();
        __syncthreads();

        const uint32_t sb  = stg[ch % NSTAGES];
        const uint32_t aA  = sb;
        const uint32_t aBh = sb + TILE_BYTES;
        const uint32_t aBl = sb + 2 * TILE_BYTES;

#pragma unroll
        for (int ks = 0; ks < 4; ks++) {
            uint32_t af[4][4], bh[2][4], bl[2][4];
#pragma unroll
            for (int mt = 0; mt < 4; mt++) {
                int row = wm * 64 + mt * 16 + a_r;
                int kb  = ks * 2 + a_kh;
                uint32_t off = (row << 7) + ((kb ^ (row & 7)) << 4);
                ldmx4(af[mt], aA + off);
            }
#pragma unroll
            for (int p = 0; p < 2; p++) {
                int row = wn * 32 + p * 16 + b_r;
                int kb  = ks * 2 + b_kh;
                uint32_t off = (row << 7) + ((kb ^ (row & 7)) << 4);
                ldmx4(bh[p], aBh + off);
                ldmx4(bl[p], aBl + off);
            }
#pragma unroll
            for (int mt = 0; mt < 4; mt++)
#pragma unroll
                for (int nt = 0; nt < 4; nt++) {
                    int p = nt >> 1, o = (nt & 1) * 2;
                    mma_f16(acc[mt][nt], af[mt], bh[p][o], bh[p][o + 1]);
                    mma_f16(acc[mt][nt], af[mt], bl[p][o], bl[p][o + 1]);
                }
        }
        __syncthreads();
    }

    const int qr = lid >> 2, qc = lid & 3;

    if (mode == 1) {
        // ---- fused LSTM epilogue: stage raw acc, then pointwise ----
#pragma unroll
        for (int mt = 0; mt < 4; mt++)
#pragma unroll
            for (int nt = 0; nt < 4; nt++)
#pragma unroll
                for (int half = 0; half < 2; half++) {
                    int r = wm * 64 + mt * 16 + qr + half * 8;
                    int n = wn * 32 + nt * 8 + qc * 2;
                    stage_f[r * 132 + n]     = acc[mt][nt][half * 2];
                    stage_f[r * 132 + n + 1] = acc[mt][nt][half * 2 + 1];
                }
        __syncthreads();

        // pointwise: tile cols = 32 hidden units x 4 gates (permuted layout)
        const int j0 = n0 >> 2;
#pragma unroll
        for (int i = tid; i < 4096; i += 256) {
            int r  = i >> 5;
            int jj = i & 31;
            int b  = m0 + r;
            int j  = j0 + jj;
            float4 a4 = *(const float4*)&stage_f[r * 132 + jj * 4];
            const float4 gx = *(const float4*)(g_gx + ((size_t)b * T_ + t) * G_ + n0 + jj * 4);
            float gi = a4.x + gx.x + bias[j];
            float gf = a4.y + gx.y + bias[j +     H_];
            float gg = a4.z + gx.z + bias[j + 2 * H_];
            float go = a4.w + gx.w + bias[j + 3 * H_];

            float i_ = 1.0f / (1.0f + expf(-gi));
            float f_ = 1.0f / (1.0f + expf(-gf));
            float g_ = tanhf(gg);
            float o_ = 1.0f / (1.0f + expf(-go));

            int idx = b * H_ + j;
            float c = f_ * g_c[idx] + i_ * g_;
            float h = o_ * tanhf(c);
            g_c[idx] = c;

            size_t oo = ((size_t)b * T_ + t) * H_ + j;
            outp[oo] = h;                         // fp32 hiddens (output)
            g_H[oo]  = __float2half_rn(h);
        }
        return;
    }

    // ---- modes 0 / 2: direct fragment store ----
#pragma unroll
    for (int mt = 0; mt < 4; mt++)
#pragma unroll
        for (int nt = 0; nt < 4; nt++)
#pragma unroll
            for (int half = 0; half < 2; half++) {
                int m = m0 + wm * 64 + mt * 16 + qr + half * 8;
                int n = n0 + wn * 32 + nt * 8 + qc * 2;
                float v0 = acc[mt][nt][half * 2];
                float v1 = acc[mt][nt][half * 2 + 1];
                if (mode == 2) {
                    if (n < NC_)     outp[(size_t)m * NC_ + n]     = v0 + bias[n];
                    if (n + 1 < NC_) outp[(size_t)m * NC_ + n + 1] = v1 + bias[n + 1];
                } else {
                    // permuted bias: dest col n holds gate (n&3) of unit (n>>2)
                    float b0 = bias[(n & 3) * H_ + (n >> 2)];
                    float b1 = bias[((n + 1) & 3) * H_ + ((n + 1) >> 2)];
                    *(float2*)(g_gx + (size_t)m * G_ + n) = make_float2(v0 + b0, v1 + b1);
                }
            }
}

// ---------------------------------------------------------------------------
// t = 0 step: h = 0, so gates = gx (permuted, bih included) + bhh
// ---------------------------------------------------------------------------
__global__ void lstm_t0(float* __restrict__ out_hid, const float* __restrict__ bhh)
{
    int i = blockIdx.x * blockDim.x + threadIdx.x;   // B*H
    int b = i >> 9;
    int j = i & 511;

    const float4 g4 = *(const float4*)(g_gx + (size_t)b * T_ * G_ + 4 * j);
    float gi = g4.x + bhh[j];
    float gf = g4.y + bhh[j +     H_];
    float gg = g4.z + bhh[j + 2 * H_];
    float go = g4.w + bhh[j + 3 * H_];

    float i_ = 1.0f / (1.0f + expf(-gi));
    float f_ = 1.0f / (1.0f + expf(-gf));
    float g_ = tanhf(gg);
    float o_ = 1.0f / (1.0f + expf(-go));

    float c = i_ * g_;          // c_prev = 0
    float h = o_ * tanhf(c);
    g_c[i] = c;

    size_t o = (size_t)b * T_ * H_ + j;   // t = 0
    out_hid[o] = h;
    g_H[o] = __float2half_rn(h);
}

// ---------------------------------------------------------------------------
// Launch: zero -> converts -> gx GEMM -> t0 -> 25 fused steps -> probs GEMM
// d_out = [probs (B*T*97) | output_hiddens (B*T*512)]
// ---------------------------------------------------------------------------
extern "C" void kernel_launch(void* const* d_in, const int* in_sizes, int n_in,
                              void* d_out, int out_size)
{
    const float* bh   = (const float*)d_in[0];
    const int*   text = (const int*)  d_in[1];
    const float* emb  = (const float*)d_in[2];
    const float* Wih  = (const float*)d_in[3];
    const float* Whh  = (const float*)d_in[4];
    const float* bih  = (const float*)d_in[5];
    const float* bhh  = (const float*)d_in[6];
    const float* Wg   = (const float*)d_in[7];
    const float* bg   = (const float*)d_in[8];

    float* probs = (float*)d_out;                     // [M1, 97]
    float* hid   = probs + (size_t)M1_ * NC_;         // [M1, 512]

    (void)in_sizes; (void)n_in; (void)out_size;

    cudaFuncSetAttribute((const void*)mma_gemm_kernel,
                         cudaFuncAttributeMaxDynamicSharedMemorySize, SMEM_DYN);

    zero_c_kernel<<<(B_ * H_ / 4) / 256, 256>>>();
    convert_x_kernel<<<M1_, K1_ / 4>>>(bh, text, emb);
    convert_w_kernel<<<G_,  K1_ / 4>>>(Wih, 0, G_,  K1_);
    convert_w_kernel<<<G_,  H_  / 4>>>(Whh, 1, G_,  H_);
    convert_w_kernel<<<128, H_  / 4>>>(Wg,  2, NC_, H_);

    // gx: M=106496 x N=2048, K=768.  n-tiles fastest => A tile L2-resident.
    mma_gemm_kernel<<<dim3(16, 832), 256, SMEM_DYN>>>(0, 0, bih, nullptr);

    lstm_t0<<<(B_ * H_) / 256, 256>>>(hid, bhh);
    for (int t = 1; t < T_; t++)
        mma_gemm_kernel<<<dim3(16, 32), 256, SMEM_DYN>>>(1, t, bhh, hid);

    // probs: N=97 padded to one 128-tile
    mma_gemm_kernel<<<dim3(1, 832), 256, SMEM_DYN>>>(2, 0, bg, probs);
}

// round 10
// speedup vs baseline: 5.7748x; 1.9332x over previous
#include <cuda_runtime.h>
#include <cuda_fp16.h>
#include <stdint.h>
#include <math.h>

// Problem constants
#define B_   4096
#define T_   26
#define IN_  512
#define H_   512
#define NC_  97
#define NE_  256
#define K1_  (IN_ + NE_)   // 768
#define G_   (4 * H_)      // 2048
#define M1_  (B_ * T_)     // 106496

// Pipeline: 3 stages x 2 tiles (A, B) x 16KB = 96KB  -> 2 CTAs/SM
#define TILE_BYTES  16384
#define STAGE_BYTES (2 * TILE_BYTES)
#define NSTAGES     3
#define SMEM_DYN    (NSTAGES * STAGE_BYTES + 128)

// ---------------------------------------------------------------------------
// Scratch (device globals: no allocation allowed anywhere)
// ---------------------------------------------------------------------------
// g_gx stored in PERMUTED gate order: col n holds gate (n&3) of unit (n>>2).
__device__ float g_gx[(size_t)M1_ * G_];
__device__ float g_c[B_ * H_];                    // cell state
__device__ __half g_x[(size_t)M1_ * K1_];         // x (concat) fp16
__device__ __half g_H[(size_t)M1_ * H_];          // hiddens fp16 [b*T+t, H]
__device__ __half g_Wih[G_ * K1_];                // weights fp16 (single term)
__device__ __half g_Whh[G_ * H_];
__device__ __half g_Wg[128 * H_];                 // W_gen padded to 128 rows

// ---------------------------------------------------------------------------
// PTX helpers (compute_103-safe: ldmatrix + mma.sync + cp.async)
// ---------------------------------------------------------------------------
__device__ __forceinline__ uint32_t smem_u32(const void* p) {
    uint32_t a;
    asm("{ .reg .u64 t; cvta.to.shared.u64 t, %1; cvt.u32.u64 %0, t; }"
        : "=r"(a) : "l"(p));
    return a;
}

__device__ __forceinline__ void ldmx4(uint32_t* r, uint32_t addr) {
    asm volatile("ldmatrix.sync.aligned.m8n8.x4.shared.b16 {%0,%1,%2,%3}, [%4];"
                 : "=r"(r[0]), "=r"(r[1]), "=r"(r[2]), "=r"(r[3]) : "r"(addr));
}

__device__ __forceinline__ void mma_f16(float* d, const uint32_t* a,
                                        uint32_t b0, uint32_t b1) {
    asm volatile(
        "mma.sync.aligned.m16n8k16.row.col.f32.f16.f16.f32 "
        "{%0,%1,%2,%3}, {%4,%5,%6,%7}, {%8,%9}, {%0,%1,%2,%3};"
        : "+f"(d[0]), "+f"(d[1]), "+f"(d[2]), "+f"(d[3])
        : "r"(a[0]), "r"(a[1]), "r"(a[2]), "r"(a[3]), "r"(b0), "r"(b1));
}

__device__ __forceinline__ void cp16(uint32_t s, const void* g) {
    asm volatile("cp.async.cg.shared.global [%0], [%1], 16;"
                 :: "r"(s), "l"(g) : "memory");
}
__device__ __forceinline__ void cp_commit() {
    asm volatile("cp.async.commit_group;" ::: "memory");
}
template <int N>
__device__ __forceinline__ void cp_wait() {
    asm volatile("cp.async.wait_group %0;" :: "n"(N) : "memory");
}

// ---------------------------------------------------------------------------
// Small prep kernels
// ---------------------------------------------------------------------------
__global__ void zero_c_kernel() {
    int i = blockIdx.x * blockDim.x + threadIdx.x;
    ((float4*)g_c)[i] = make_float4(0.f, 0.f, 0.f, 0.f);
}

// x = concat(batch_H, emb[text]) -> fp16.  grid = M1, block = 192
__global__ void convert_x_kernel(const float* __restrict__ bh,
                                 const int* __restrict__ text,
                                 const float* __restrict__ emb) {
    int m = blockIdx.x;
    int k = threadIdx.x * 4;
    float4 v;
    if (k < IN_) v = *(const float4*)(bh + (size_t)m * IN_ + k);
    else         v = *(const float4*)(emb + (size_t)text[m] * NE_ + (k - IN_));
    size_t o = (size_t)m * K1_ + k;
    g_x[o]   = __float2half_rn(v.x);
    g_x[o+1] = __float2half_rn(v.y);
    g_x[o+2] = __float2half_rn(v.z);
    g_x[o+3] = __float2half_rn(v.w);
}

// Weight -> fp16.  which: 0=Wih 1=Whh (gate-permuted) 2=Wgen (padded)
__global__ void convert_w_kernel(const float* __restrict__ src, int which,
                                 int Rvalid, int K) {
    int r = blockIdx.x;                       // destination row
    int k = threadIdx.x * 4;
    int sr = (which < 2) ? ((r & 3) * H_ + (r >> 2)) : r;   // gate permutation
    float4 v = make_float4(0.f, 0.f, 0.f, 0.f);
    if (sr < Rvalid) v = *(const float4*)(src + (size_t)sr * K + k);
    __half* dst = (which == 0) ? g_Wih : (which == 1) ? g_Whh : g_Wg;
    size_t o = (size_t)r * K + k;
    dst[o]   = __float2half_rn(v.x);
    dst[o+1] = __float2half_rn(v.y);
    dst[o+2] = __float2half_rn(v.z);
    dst[o+3] = __float2half_rn(v.w);
}

// ---------------------------------------------------------------------------
// fp16 GEMM via mma.sync, 3-stage cp.async pipeline, occ 2.
// mode 0: gx    = x @ Wih^T (perm)  (K=768) -> g_gx (+bih perm)
// mode 1: gates = h(t-1) @ Whh^T (perm), FUSED LSTM pointwise epilogue
// mode 2: probs = H @ Wgen^T        (K=512) -> outp (+bg, n<97)
// 8 warps: warp tile 64(m) x 32(n); K-chunk 64.
// ---------------------------------------------------------------------------
__global__ void __launch_bounds__(256, 2)
mma_gemm_kernel(int mode, int t, const float* __restrict__ bias,
                float* __restrict__ outp)
{
    extern __shared__ char dsm[];

    const int tid = threadIdx.x;
    const int wid = tid >> 5;
    const int lid = tid & 31;
    const int wm  = wid & 1;    // 2 m-blocks of 64
    const int wn  = wid >> 1;   // 4 n-blocks of 32
    const int n0  = blockIdx.x * 128;
    const int m0  = blockIdx.y * 128;

    const __half *A, *Bp;
    long lda, ldb;
    int K;
    if (mode == 0) {
        A = g_x; lda = K1_;
        Bp = g_Wih; ldb = K1_; K = K1_;
    } else if (mode == 1) {
        A = g_H + (size_t)(t - 1) * H_;     // row b -> (b*T + t-1)*H
        lda = (long)T_ * H_;
        Bp = g_Whh; ldb = H_; K = H_;
    } else {
        A = g_H; lda = H_;
        Bp = g_Wg; ldb = H_; K = H_;
    }

    uint32_t raw  = smem_u32(dsm);
    uint32_t base = (raw + 127) & ~127u;
    float* stage_f = (float*)(dsm + (base - raw));   // epilogue stage (reuse)
    uint32_t stg[NSTAGES];
#pragma unroll
    for (int s = 0; s < NSTAGES; s++) stg[s] = base + s * STAGE_BYTES;

    float acc[4][4][4];
#pragma unroll
    for (int mt = 0; mt < 4; mt++)
#pragma unroll
        for (int nt = 0; nt < 4; nt++)
#pragma unroll
            for (int r = 0; r < 4; r++) acc[mt][nt][r] = 0.0f;

    // per-lane ldmatrix address components
    const int a_r  = lid & 15;
    const int a_kh = lid >> 4;
    const int b_r  = (lid & 7) + ((lid & 16) ? 8 : 0);
    const int b_kh = (lid >> 3) & 1;

    const int nchunks = K >> 6;

    // ---- async stage loader: 2 tiles x (128 rows x 128B), XOR-swizzled ----
    auto load_stage = [&](int ch, uint32_t sb) {
        const int k0 = ch * 64;
#pragma unroll
        for (int i = tid; i < 1024; i += 256) {
            int r = i >> 3, u = i & 7;
            uint32_t sw = (r << 7) + ((u ^ (r & 7)) << 4);
            cp16(sb + sw,              A  + (size_t)(m0 + r) * lda + k0 + u * 8);
            cp16(sb + TILE_BYTES + sw, Bp + (size_t)(n0 + r) * ldb + k0 + u * 8);
        }
    };

    // prologue: NSTAGES-1 stages in flight
#pragma unroll
    for (int s = 0; s < NSTAGES - 1; s++) {
        if (s < nchunks) load_stage(s, stg[s]);
        cp_commit();
    }

    for (int ch = 0; ch < nchunks; ch++) {
        if (ch + NSTAGES - 1 < nchunks)
            load_stage(ch + NSTAGES - 1, stg[(ch + NSTAGES - 1) % NSTAGES]);
        cp_commit();
        cp_wait<NSTAGES - 1>();
        __syncthreads();

        const uint32_t sb = stg[ch % NSTAGES];
        const uint32_t aA = sb;
        const uint32_t aB = sb + TILE_BYTES;

#pragma unroll
        for (int ks = 0; ks < 4; ks++) {
            uint32_t af[4][4], bf[2][4];
#pragma unroll
            for (int mt = 0; mt < 4; mt++) {
                int row = wm * 64 + mt * 16 + a_r;
                int kb  = ks * 2 + a_kh;
                uint32_t off = (row << 7) + ((kb ^ (row & 7)) << 4);
                ldmx4(af[mt], aA + off);
            }
#pragma unroll
            for (int p = 0; p < 2; p++) {
                int row = wn * 32 + p * 16 + b_r;
                int kb  = ks * 2 + b_kh;
                uint32_t off = (row << 7) + ((kb ^ (row & 7)) << 4);
                ldmx4(bf[p], aB + off);
            }
#pragma unroll
            for (int mt = 0; mt < 4; mt++)
#pragma unroll
                for (int nt = 0; nt < 4; nt++) {
                    int p = nt >> 1, o = (nt & 1) * 2;
                    mma_f16(acc[mt][nt], af[mt], bf[p][o], bf[p][o + 1]);
                }
        }
        __syncthreads();
    }

    const int qr = lid >> 2, qc = lid & 3;

    if (mode == 1) {
        // ---- fused LSTM epilogue: stage raw acc, then pointwise ----
#pragma unroll
        for (int mt = 0; mt < 4; mt++)
#pragma unroll
            for (int nt = 0; nt < 4; nt++)
#pragma unroll
                for (int half = 0; half < 2; half++) {
                    int r = wm * 64 + mt * 16 + qr + half * 8;
                    int n = wn * 32 + nt * 8 + qc * 2;
                    stage_f[r * 132 + n]     = acc[mt][nt][half * 2];
                    stage_f[r * 132 + n + 1] = acc[mt][nt][half * 2 + 1];
                }
        __syncthreads();

        // pointwise: tile cols = 32 hidden units x 4 gates (permuted layout)
        const int j0 = n0 >> 2;
#pragma unroll
        for (int i = tid; i < 4096; i += 256) {
            int r  = i >> 5;
            int jj = i & 31;
            int b  = m0 + r;
            int j  = j0 + jj;
            float4 a4 = *(const float4*)&stage_f[r * 132 + jj * 4];
            const float4 gx = *(const float4*)(g_gx + ((size_t)b * T_ + t) * G_ + n0 + jj * 4);
            float gi = a4.x + gx.x + bias[j];
            float gf = a4.y + gx.y + bias[j +     H_];
            float gg = a4.z + gx.z + bias[j + 2 * H_];
            float go = a4.w + gx.w + bias[j + 3 * H_];

            float i_ = 1.0f / (1.0f + expf(-gi));
            float f_ = 1.0f / (1.0f + expf(-gf));
            float g_ = tanhf(gg);
            float o_ = 1.0f / (1.0f + expf(-go));

            int idx = b * H_ + j;
            float c = f_ * g_c[idx] + i_ * g_;
            float h = o_ * tanhf(c);
            g_c[idx] = c;

            size_t oo = ((size_t)b * T_ + t) * H_ + j;
            outp[oo] = h;                         // fp32 hiddens (output)
            g_H[oo]  = __float2half_rn(h);
        }
        return;
    }

    // ---- modes 0 / 2: direct fragment store ----
#pragma unroll
    for (int mt = 0; mt < 4; mt++)
#pragma unroll
        for (int nt = 0; nt < 4; nt++)
#pragma unroll
            for (int half = 0; half < 2; half++) {
                int m = m0 + wm * 64 + mt * 16 + qr + half * 8;
                int n = n0 + wn * 32 + nt * 8 + qc * 2;
                float v0 = acc[mt][nt][half * 2];
                float v1 = acc[mt][nt][half * 2 + 1];
                if (mode == 2) {
                    if (n < NC_)     outp[(size_t)m * NC_ + n]     = v0 + bias[n];
                    if (n + 1 < NC_) outp[(size_t)m * NC_ + n + 1] = v1 + bias[n + 1];
                } else {
                    // permuted bias: dest col n holds gate (n&3) of unit (n>>2)
                    float b0 = bias[(n & 3) * H_ + (n >> 2)];
                    float b1 = bias[((n + 1) & 3) * H_ + ((n + 1) >> 2)];
                    *(float2*)(g_gx + (size_t)m * G_ + n) = make_float2(v0 + b0, v1 + b1);
                }
            }
}

// ---------------------------------------------------------------------------
// t = 0 step: h = 0, so gates = gx (permuted, bih included) + bhh
// ---------------------------------------------------------------------------
__global__ void lstm_t0(float* __restrict__ out_hid, const float* __restrict__ bhh)
{
    int i = blockIdx.x * blockDim.x + threadIdx.x;   // B*H
    int b = i >> 9;
    int j = i & 511;

    const float4 g4 = *(const float4*)(g_gx + (size_t)b * T_ * G_ + 4 * j);
    float gi = g4.x + bhh[j];
    float gf = g4.y + bhh[j +     H_];
    float gg = g4.z + bhh[j + 2 * H_];
    float go = g4.w + bhh[j + 3 * H_];

    float i_ = 1.0f / (1.0f + expf(-gi));
    float f_ = 1.0f / (1.0f + expf(-gf));
    float g_ = tanhf(gg);
    float o_ = 1.0f / (1.0f + expf(-go));

    float c = i_ * g_;          // c_prev = 0
    float h = o_ * tanhf(c);
    g_c[i] = c;

    size_t o = (size_t)b * T_ * H_ + j;   // t = 0
    out_hid[o] = h;
    g_H[o] = __float2half_rn(h);
}

// ---------------------------------------------------------------------------
// Launch: zero -> converts -> gx GEMM -> t0 -> 25 fused steps -> probs GEMM
// d_out = [probs (B*T*97) | output_hiddens (B*T*512)]
// ---------------------------------------------------------------------------
extern "C" void kernel_launch(void* const* d_in, const int* in_sizes, int n_in,
                              void* d_out, int out_size)
{
    const float* bh   = (const float*)d_in[0];
    const int*   text = (const int*)  d_in[1];
    const float* emb  = (const float*)d_in[2];
    const float* Wih  = (const float*)d_in[3];
    const float* Whh  = (const float*)d_in[4];
    const float* bih  = (const float*)d_in[5];
    const float* bhh  = (const float*)d_in[6];
    const float* Wg   = (const float*)d_in[7];
    const float* bg   = (const float*)d_in[8];

    float* probs = (float*)d_out;                     // [M1, 97]
    float* hid   = probs + (size_t)M1_ * NC_;         // [M1, 512]

    (void)in_sizes; (void)n_in; (void)out_size;

    cudaFuncSetAttribute((const void*)mma_gemm_kernel,
                         cudaFuncAttributeMaxDynamicSharedMemorySize, SMEM_DYN);

    zero_c_kernel<<<(B_ * H_ / 4) / 256, 256>>>();
    convert_x_kernel<<<M1_, K1_ / 4>>>(bh, text, emb);
    convert_w_kernel<<<G_,  K1_ / 4>>>(Wih, 0, G_,  K1_);
    convert_w_kernel<<<G_,  H_  / 4>>>(Whh, 1, G_,  H_);
    convert_w_kernel<<<128, H_  / 4>>>(Wg,  2, NC_, H_);

    // gx: M=106496 x N=2048, K=768.  n-tiles fastest => A tile L2-resident.
    mma_gemm_kernel<<<dim3(16, 832), 256, SMEM_DYN>>>(0, 0, bih, nullptr);

    lstm_t0<<<(B_ * H_) / 256, 256>>>(hid, bhh);
    for (int t = 1; t < T_; t++)
        mma_gemm_kernel<<<dim3(16, 32), 256, SMEM_DYN>>>(1, t, bhh, hid);

    // probs: N=97 padded to one 128-tile
    mma_gemm_kernel<<<dim3(1, 832), 256, SMEM_DYN>>>(2, 0, bg, probs);
}

// round 11
// speedup vs baseline: 6.3383x; 1.0976x over previous
#include <cuda_runtime.h>
#include <cuda_fp16.h>
#include <stdint.h>
#include <math.h>

// Problem constants
#define B_   4096
#define T_   26
#define IN_  512
#define H_   512
#define NC_  97
#define NE_  256
#define K1_  (IN_ + NE_)   // 768
#define G_   (4 * H_)      // 2048
#define M1_  (B_ * T_)     // 106496

// Pipeline: 3 stages x 2 tiles (A, B) x 16KB = 96KB  -> 2 CTAs/SM
#define TILE_BYTES  16384
#define STAGE_BYTES (2 * TILE_BYTES)
#define NSTAGES     3
#define SMEM_DYN    (NSTAGES * STAGE_BYTES + 128)

// Persistent recurrent kernel decomposition
#define GROUPS      32     // batch m-tiles (4096 / 128)
#define GROUP_CTAS  8      // CTAs per group; each owns 2 n-tiles (64 units)

// ---------------------------------------------------------------------------
// Scratch (device globals: no allocation allowed anywhere)
// ---------------------------------------------------------------------------
// g_gx16 stored fp16, PERMUTED gate order: col n = gate (n&3) of unit (n>>2).
__device__ __half g_gx16[(size_t)M1_ * G_];
__device__ float g_c[B_ * H_];                    // cell state
__device__ __half g_x[(size_t)M1_ * K1_];         // x (concat) fp16
__device__ __half g_H[(size_t)M1_ * H_];          // hiddens fp16 [b*T+t, H]
__device__ __half g_Wih[G_ * K1_];                // weights fp16
__device__ __half g_Whh[G_ * H_];
__device__ __half g_Wg[128 * H_];                 // W_gen padded to 128 rows
__device__ int   g_bar[GROUPS];                   // per-group arrival counters

// ---------------------------------------------------------------------------
// PTX helpers (compute_103-safe: ldmatrix + mma.sync + cp.async)
// ---------------------------------------------------------------------------
__device__ __forceinline__ uint32_t smem_u32(const void* p) {
    uint32_t a;
    asm("{ .reg .u64 t; cvta.to.shared.u64 t, %1; cvt.u32.u64 %0, t; }"
        : "=r"(a) : "l"(p));
    return a;
}

__device__ __forceinline__ void ldmx4(uint32_t* r, uint32_t addr) {
    asm volatile("ldmatrix.sync.aligned.m8n8.x4.shared.b16 {%0,%1,%2,%3}, [%4];"
                 : "=r"(r[0]), "=r"(r[1]), "=r"(r[2]), "=r"(r[3]) : "r"(addr));
}

__device__ __forceinline__ void mma_f16(float* d, const uint32_t* a,
                                        uint32_t b0, uint32_t b1) {
    asm volatile(
        "mma.sync.aligned.m16n8k16.row.col.f32.f16.f16.f32 "
        "{%0,%1,%2,%3}, {%4,%5,%6,%7}, {%8,%9}, {%0,%1,%2,%3};"
        : "+f"(d[0]), "+f"(d[1]), "+f"(d[2]), "+f"(d[3])
        : "r"(a[0]), "r"(a[1]), "r"(a[2]), "r"(a[3]), "r"(b0), "r"(b1));
}

__device__ __forceinline__ void cp16(uint32_t s, const void* g) {
    asm volatile("cp.async.cg.shared.global [%0], [%1], 16;"
                 :: "r"(s), "l"(g) : "memory");
}
__device__ __forceinline__ void cp_commit() {
    asm volatile("cp.async.commit_group;" ::: "memory");
}
template <int N>
__device__ __forceinline__ void cp_wait() {
    asm volatile("cp.async.wait_group %0;" :: "n"(N) : "memory");
}

// ---------------------------------------------------------------------------
// Small prep kernels
// ---------------------------------------------------------------------------
__global__ void zero_state_kernel() {
    int i = blockIdx.x * blockDim.x + threadIdx.x;
    ((float4*)g_c)[i] = make_float4(0.f, 0.f, 0.f, 0.f);
    if (blockIdx.x == 0 && threadIdx.x < GROUPS) g_bar[threadIdx.x] = 0;
}

// x = concat(batch_H, emb[text]) -> fp16.  grid = M1, block = 192
__global__ void convert_x_kernel(const float* __restrict__ bh,
                                 const int* __restrict__ text,
                                 const float* __restrict__ emb) {
    int m = blockIdx.x;
    int k = threadIdx.x * 4;
    float4 v;
    if (k < IN_) v = *(const float4*)(bh + (size_t)m * IN_ + k);
    else         v = *(const float4*)(emb + (size_t)text[m] * NE_ + (k - IN_));
    size_t o = (size_t)m * K1_ + k;
    g_x[o]   = __float2half_rn(v.x);
    g_x[o+1] = __float2half_rn(v.y);
    g_x[o+2] = __float2half_rn(v.z);
    g_x[o+3] = __float2half_rn(v.w);
}

// Weight -> fp16.  which: 0=Wih 1=Whh (gate-permuted) 2=Wgen (padded)
__global__ void convert_w_kernel(const float* __restrict__ src, int which,
                                 int Rvalid, int K) {
    int r = blockIdx.x;                       // destination row
    int k = threadIdx.x * 4;
    int sr = (which < 2) ? ((r & 3) * H_ + (r >> 2)) : r;   // gate permutation
    float4 v = make_float4(0.f, 0.f, 0.f, 0.f);
    if (sr < Rvalid) v = *(const float4*)(src + (size_t)sr * K + k);
    __half* dst = (which == 0) ? g_Wih : (which == 1) ? g_Whh : g_Wg;
    size_t o = (size_t)r * K + k;
    dst[o]   = __float2half_rn(v.x);
    dst[o+1] = __float2half_rn(v.y);
    dst[o+2] = __float2half_rn(v.z);
    dst[o+3] = __float2half_rn(v.w);
}

// ---------------------------------------------------------------------------
// fp16 GEMM via mma.sync, 3-stage cp.async pipeline, occ 2.
// mode 0: gx    = x @ Wih^T (perm)  (K=768) -> g_gx16 (+bih perm, fp16)
// mode 2: probs = H @ Wgen^T        (K=512) -> outp   (+bg, n<97)
// 8 warps: warp tile 64(m) x 32(n); K-chunk 64.
// ---------------------------------------------------------------------------
__global__ void __launch_bounds__(256, 2)
mma_gemm_kernel(int mode, const float* __restrict__ bias,
                float* __restrict__ outp)
{
    extern __shared__ char dsm[];

    const int tid = threadIdx.x;
    const int wid = tid >> 5;
    const int lid = tid & 31;
    const int wm  = wid & 1;
    const int wn  = wid >> 1;
    const int n0  = blockIdx.x * 128;
    const int m0  = blockIdx.y * 128;

    const __half *A, *Bp;
    long lda, ldb;
    int K;
    if (mode == 0) { A = g_x; lda = K1_; Bp = g_Wih; ldb = K1_; K = K1_; }
    else           { A = g_H; lda = H_;  Bp = g_Wg;  ldb = H_;  K = H_;  }

    uint32_t raw  = smem_u32(dsm);
    uint32_t base = (raw + 127) & ~127u;
    uint32_t stg[NSTAGES];
#pragma unroll
    for (int s = 0; s < NSTAGES; s++) stg[s] = base + s * STAGE_BYTES;

    float acc[4][4][4];
#pragma unroll
    for (int mt = 0; mt < 4; mt++)
#pragma unroll
        for (int nt = 0; nt < 4; nt++)
#pragma unroll
            for (int r = 0; r < 4; r++) acc[mt][nt][r] = 0.0f;

    const int a_r  = lid & 15;
    const int a_kh = lid >> 4;
    const int b_r  = (lid & 7) + ((lid & 16) ? 8 : 0);
    const int b_kh = (lid >> 3) & 1;

    const int nchunks = K >> 6;

    auto load_stage = [&](int ch, uint32_t sb) {
        const int k0 = ch * 64;
#pragma unroll
        for (int i = tid; i < 1024; i += 256) {
            int r = i >> 3, u = i & 7;
            uint32_t sw = (r << 7) + ((u ^ (r & 7)) << 4);
            cp16(sb + sw,              A  + (size_t)(m0 + r) * lda + k0 + u * 8);
            cp16(sb + TILE_BYTES + sw, Bp + (size_t)(n0 + r) * ldb + k0 + u * 8);
        }
    };

#pragma unroll
    for (int s = 0; s < NSTAGES - 1; s++) {
        if (s < nchunks) load_stage(s, stg[s]);
        cp_commit();
    }

    for (int ch = 0; ch < nchunks; ch++) {
        if (ch + NSTAGES - 1 < nchunks)
            load_stage(ch + NSTAGES - 1, stg[(ch + NSTAGES - 1) % NSTAGES]);
        cp_commit();
        cp_wait<NSTAGES - 1>();
        __syncthreads();

        const uint32_t aA = stg[ch % NSTAGES];
        const uint32_t aB = aA + TILE_BYTES;

#pragma unroll
        for (int ks = 0; ks < 4; ks++) {
            uint32_t af[4][4], bf[2][4];
#pragma unroll
            for (int mt = 0; mt < 4; mt++) {
                int row = wm * 64 + mt * 16 + a_r;
                int kb  = ks * 2 + a_kh;
                ldmx4(af[mt], aA + (row << 7) + ((kb ^ (row & 7)) << 4));
            }
#pragma unroll
            for (int p = 0; p < 2; p++) {
                int row = wn * 32 + p * 16 + b_r;
                int kb  = ks * 2 + b_kh;
                ldmx4(bf[p], aB + (row << 7) + ((kb ^ (row & 7)) << 4));
            }
#pragma unroll
            for (int mt = 0; mt < 4; mt++)
#pragma unroll
                for (int nt = 0; nt < 4; nt++) {
                    int p = nt >> 1, o = (nt & 1) * 2;
                    mma_f16(acc[mt][nt], af[mt], bf[p][o], bf[p][o + 1]);
                }
        }
        __syncthreads();
    }

    const int qr = lid >> 2, qc = lid & 3;
#pragma unroll
    for (int mt = 0; mt < 4; mt++)
#pragma unroll
        for (int nt = 0; nt < 4; nt++)
#pragma unroll
            for (int half = 0; half < 2; half++) {
                int m = m0 + wm * 64 + mt * 16 + qr + half * 8;
                int n = n0 + wn * 32 + nt * 8 + qc * 2;
                float v0 = acc[mt][nt][half * 2];
                float v1 = acc[mt][nt][half * 2 + 1];
                if (mode == 2) {
                    if (n < NC_)     outp[(size_t)m * NC_ + n]     = v0 + bias[n];
                    if (n + 1 < NC_) outp[(size_t)m * NC_ + n + 1] = v1 + bias[n + 1];
                } else {
                    // permuted bias: dest col n holds gate (n&3) of unit (n>>2)
                    float b0 = bias[(n & 3) * H_ + (n >> 2)];
                    float b1 = bias[((n + 1) & 3) * H_ + ((n + 1) >> 2)];
                    *(__half2*)(g_gx16 + (size_t)m * G_ + n) =
                        __floats2half2_rn(v0 + b0, v1 + b1);
                }
            }
}

// ---------------------------------------------------------------------------
// Persistent recurrent kernel: 256 CTAs = 32 groups x 8.
// Group g owns batch rows [g*128, g*128+128); CTA sub owns n-tiles
// sub*256 and sub*256+128 (64 hidden units).  25 steps with per-group
// atomic barrier (h is batch-local; no global sync needed).
// ---------------------------------------------------------------------------
__global__ void __launch_bounds__(256, 2)
recurrent_kernel(float* __restrict__ out_hid, const float* __restrict__ bhh)
{
    extern __shared__ char dsm[];

    const int tid = threadIdx.x;
    const int wid = tid >> 5;
    const int lid = tid & 31;
    const int wm  = wid & 1;
    const int wn  = wid >> 1;
    const int grp = blockIdx.x >> 3;
    const int sub = blockIdx.x & 7;
    const int m0  = grp * 128;

    uint32_t raw  = smem_u32(dsm);
    uint32_t base = (raw + 127) & ~127u;
    float* stage_f = (float*)(dsm + (base - raw));
    uint32_t stg[NSTAGES];
#pragma unroll
    for (int s = 0; s < NSTAGES; s++) stg[s] = base + s * STAGE_BYTES;

    const int a_r  = lid & 15;
    const int a_kh = lid >> 4;
    const int b_r  = (lid & 7) + ((lid & 16) ? 8 : 0);
    const int b_kh = (lid >> 3) & 1;
    const int qr = lid >> 2, qc = lid & 3;

    for (int t = 1; t < T_; t++) {
        const __half* A = g_H + (size_t)(t - 1) * H_;   // row b -> (b*T+t-1)*H
        const long lda = (long)T_ * H_;

#pragma unroll 1
        for (int tile = 0; tile < 2; tile++) {
            const int n0 = sub * 256 + tile * 128;

            float acc[4][4][4];
#pragma unroll
            for (int mt = 0; mt < 4; mt++)
#pragma unroll
                for (int nt = 0; nt < 4; nt++)
#pragma unroll
                    for (int r = 0; r < 4; r++) acc[mt][nt][r] = 0.0f;

            auto load_stage = [&](int ch, uint32_t sb) {
                const int k0 = ch * 64;
#pragma unroll
                for (int i = tid; i < 1024; i += 256) {
                    int r = i >> 3, u = i & 7;
                    uint32_t sw = (r << 7) + ((u ^ (r & 7)) << 4);
                    cp16(sb + sw,              A + (size_t)(m0 + r) * lda + k0 + u * 8);
                    cp16(sb + TILE_BYTES + sw, g_Whh + (size_t)(n0 + r) * H_ + k0 + u * 8);
                }
            };

            load_stage(0, stg[0]); cp_commit();
            load_stage(1, stg[1]); cp_commit();

            for (int ch = 0; ch < 8; ch++) {   // K = 512 -> 8 chunks
                if (ch + 2 < 8) load_stage(ch + 2, stg[(ch + 2) % NSTAGES]);
                cp_commit();
                cp_wait<2>();
                __syncthreads();

                const uint32_t aA = stg[ch % NSTAGES];
                const uint32_t aB = aA + TILE_BYTES;
#pragma unroll
                for (int ks = 0; ks < 4; ks++) {
                    uint32_t af[4][4], bf[2][4];
#pragma unroll
                    for (int mt = 0; mt < 4; mt++) {
                        int row = wm * 64 + mt * 16 + a_r;
                        int kb  = ks * 2 + a_kh;
                        ldmx4(af[mt], aA + (row << 7) + ((kb ^ (row & 7)) << 4));
                    }
#pragma unroll
                    for (int p = 0; p < 2; p++) {
                        int row = wn * 32 + p * 16 + b_r;
                        int kb  = ks * 2 + b_kh;
                        ldmx4(bf[p], aB + (row << 7) + ((kb ^ (row & 7)) << 4));
                    }
#pragma unroll
                    for (int mt = 0; mt < 4; mt++)
#pragma unroll
                        for (int nt = 0; nt < 4; nt++) {
                            int p = nt >> 1, o = (nt & 1) * 2;
                            mma_f16(acc[mt][nt], af[mt], bf[p][o], bf[p][o + 1]);
                        }
                }
                __syncthreads();
            }
            cp_wait<0>();

            // stage acc -> smem, then fused pointwise for these 32 units
#pragma unroll
            for (int mt = 0; mt < 4; mt++)
#pragma unroll
                for (int nt = 0; nt < 4; nt++)
#pragma unroll
                    for (int half = 0; half < 2; half++) {
                        int r = wm * 64 + mt * 16 + qr + half * 8;
                        int n = wn * 32 + nt * 8 + qc * 2;
                        stage_f[r * 132 + n]     = acc[mt][nt][half * 2];
                        stage_f[r * 132 + n + 1] = acc[mt][nt][half * 2 + 1];
                    }
            __syncthreads();

            const int j0 = n0 >> 2;
#pragma unroll
            for (int i = tid; i < 4096; i += 256) {
                int r  = i >> 5;
                int jj = i & 31;
                int b  = m0 + r;
                int j  = j0 + jj;
                float4 a4 = *(const float4*)&stage_f[r * 132 + jj * 4];
                const __half2* gxp = (const __half2*)(
                    g_gx16 + ((size_t)b * T_ + t) * G_ + n0 + jj * 4);
                float2 gx01 = __half22float2(gxp[0]);
                float2 gx23 = __half22float2(gxp[1]);
                float gi = a4.x + gx01.x + bhh[j];
                float gf = a4.y + gx01.y + bhh[j +     H_];
                float gg = a4.z + gx23.x + bhh[j + 2 * H_];
                float go = a4.w + gx23.y + bhh[j + 3 * H_];

                float i_ = 1.0f / (1.0f + expf(-gi));
                float f_ = 1.0f / (1.0f + expf(-gf));
                float g_ = tanhf(gg);
                float o_ = 1.0f / (1.0f + expf(-go));

                int idx = b * H_ + j;
                float c = f_ * g_c[idx] + i_ * g_;
                float h = o_ * tanhf(c);
                g_c[idx] = c;

                size_t oo = ((size_t)b * T_ + t) * H_ + j;
                out_hid[oo] = h;
                g_H[oo]     = __float2half_rn(h);
            }
            __syncthreads();   // stage_f free before next tile's loads
        }

        // ---- group barrier: wait for all 8 CTAs of this group ----
        if (tid == 0) {
            __threadfence();
            atomicAdd(&g_bar[grp], 1);
            while (*(volatile int*)&g_bar[grp] < GROUP_CTAS * t)
                __nanosleep(64);
            __threadfence();
        }
        __syncthreads();
    }
}

// ---------------------------------------------------------------------------
// t = 0 step: h = 0, so gates = gx (permuted fp16, bih included) + bhh
// ---------------------------------------------------------------------------
__global__ void lstm_t0(float* __restrict__ out_hid, const float* __restrict__ bhh)
{
    int i = blockIdx.x * blockDim.x + threadIdx.x;   // B*H
    int b = i >> 9;
    int j = i & 511;

    const __half2* gxp = (const __half2*)(g_gx16 + (size_t)b * T_ * G_ + 4 * j);
    float2 g01 = __half22float2(gxp[0]);
    float2 g23 = __half22float2(gxp[1]);
    float gi = g01.x + bhh[j];
    float gf = g01.y + bhh[j +     H_];
    float gg = g23.x + bhh[j + 2 * H_];
    float go = g23.y + bhh[j + 3 * H_];

    float i_ = 1.0f / (1.0f + expf(-gi));
    float f_ = 1.0f / (1.0f + expf(-gf));
    float g_ = tanhf(gg);
    float o_ = 1.0f / (1.0f + expf(-go));

    float c = i_ * g_;          // c_prev = 0
    float h = o_ * tanhf(c);
    g_c[i] = c;

    size_t o = (size_t)b * T_ * H_ + j;   // t = 0
    out_hid[o] = h;
    g_H[o] = __float2half_rn(h);
}

// ---------------------------------------------------------------------------
// Launch: zero -> converts -> gx GEMM -> t0 -> persistent recurrent -> probs
// d_out = [probs (B*T*97) | output_hiddens (B*T*512)]
// ---------------------------------------------------------------------------
extern "C" void kernel_launch(void* const* d_in, const int* in_sizes, int n_in,
                              void* d_out, int out_size)
{
    const float* bh   = (const float*)d_in[0];
    const int*   text = (const int*)  d_in[1];
    const float* emb  = (const float*)d_in[2];
    const float* Wih  = (const float*)d_in[3];
    const float* Whh  = (const float*)d_in[4];
    const float* bih  = (const float*)d_in[5];
    const float* bhh  = (const float*)d_in[6];
    const float* Wg   = (const float*)d_in[7];
    const float* bg   = (const float*)d_in[8];

    float* probs = (float*)d_out;                     // [M1, 97]
    float* hid   = probs + (size_t)M1_ * NC_;         // [M1, 512]

    (void)in_sizes; (void)n_in; (void)out_size;

    cudaFuncSetAttribute((const void*)mma_gemm_kernel,
                         cudaFuncAttributeMaxDynamicSharedMemorySize, SMEM_DYN);
    cudaFuncSetAttribute((const void*)recurrent_kernel,
                         cudaFuncAttributeMaxDynamicSharedMemorySize, SMEM_DYN);

    zero_state_kernel<<<(B_ * H_ / 4) / 256, 256>>>();
    convert_x_kernel<<<M1_, K1_ / 4>>>(bh, text, emb);
    convert_w_kernel<<<G_,  K1_ / 4>>>(Wih, 0, G_,  K1_);
    convert_w_kernel<<<G_,  H_  / 4>>>(Whh, 1, G_,  H_);
    convert_w_kernel<<<128, H_  / 4>>>(Wg,  2, NC_, H_);

    // gx: M=106496 x N=2048, K=768.  n-tiles fastest => A tile L2-resident.
    mma_gemm_kernel<<<dim3(16, 832), 256, SMEM_DYN>>>(0, bih, nullptr);

    lstm_t0<<<(B_ * H_) / 256, 256>>>(hid, bhh);

    recurrent_kernel<<<GROUPS * GROUP_CTAS, 256, SMEM_DYN>>>(hid, bhh);

    // probs: N=97 padded to one 128-tile
    mma_gemm_kernel<<<dim3(1, 832), 256, SMEM_DYN>>>(2, bg, probs);
}